// round 9
// baseline (speedup 1.0000x reference)
#include <cuda_runtime.h>
#include <cstdint>
#include <cstddef>

#define B_  8
#define T_  1024
#define D_  1024
#define H_  16
#define HD_ 64
#define FF_ 4096
#define BT_ (B_*T_)            // 8192
#define TD3_ (3*D_)            // 3072

// ---------------- scratch (device globals: allocation-guard-safe) ----------
__device__ float g_h[(size_t)BT_ * D_];          // 32 MB  (tf32-rounded)
__device__ float g_qkv[(size_t)BT_ * TD3_];      // 96 MB  (tf32-rounded)
__device__ float g_wcat[(size_t)D_ * TD3_];      // 12 MB  (tf32-rounded)
__device__ float g_bcat[TD3_];
__device__ float g_ctx[(size_t)BT_ * D_];        // 32 MB  (tf32-rounded)
__device__ float g_ffa[(size_t)BT_ * FF_];       // 128 MB (tf32-rounded)
__device__ float g_wrnd[(size_t)D_*D_ + (size_t)D_*FF_ + (size_t)FF_*D_]; // 36 MB

// ---------------- helpers ---------------------------------------------------
__device__ __forceinline__ float geluf(float x) {
    return 0.5f * x * (1.0f + erff(x * 0.70710678118654752f));
}
__device__ __forceinline__ uint32_t f2tf(float x) {
    uint32_t r; asm("cvt.rna.tf32.f32 %0, %1;" : "=r"(r) : "f"(x)); return r;
}
__device__ __forceinline__ float rtf(float x) {
    return __uint_as_float(f2tf(x));
}
__device__ __forceinline__ void mma_tf32(float c[4], const uint32_t a[4], const uint32_t b[2]) {
    asm volatile(
        "mma.sync.aligned.m16n8k8.row.col.f32.tf32.tf32.f32 "
        "{%0,%1,%2,%3}, {%4,%5,%6,%7}, {%8,%9}, {%0,%1,%2,%3};"
        : "+f"(c[0]), "+f"(c[1]), "+f"(c[2]), "+f"(c[3])
        : "r"(a[0]), "r"(a[1]), "r"(a[2]), "r"(a[3]), "r"(b[0]), "r"(b[1]));
}
__device__ __forceinline__ void cp_async16(void* sptr, const void* gptr) {
    uint32_t s = (uint32_t)__cvta_generic_to_shared(sptr);
    asm volatile("cp.async.cg.shared.global [%0], [%1], 16;" :: "r"(s), "l"(gptr));
}
#define CP_COMMIT() asm volatile("cp.async.commit_group;")
#define CP_WAIT0()  asm volatile("cp.async.wait_group 0;")
#define CP_WAIT1()  asm volatile("cp.async.wait_group 1;")

// ---------------- weight repack: Wq/Wk/Wv [H,D,HD] -> Wcat [D, 3D] ----------
__global__ __launch_bounds__(256) void repack_kernel(
    const float* __restrict__ Wq, const float* __restrict__ Wk, const float* __restrict__ Wv,
    const float* __restrict__ bq, const float* __restrict__ bk, const float* __restrict__ bv)
{
    int t = blockIdx.x * blockDim.x + threadIdx.x;
    if (t >= D_ * TD3_) return;
    int d = t / TD3_;
    int n = t - d * TD3_;
    int part = n >> 10;
    int m = n & (D_ - 1);
    int h = m >> 6, e = m & 63;
    const float* W = (part == 0) ? Wq : (part == 1) ? Wk : Wv;
    g_wcat[t] = rtf(W[((size_t)h * D_ + d) * HD_ + e]);
    if (d == 0) {
        const float* bb = (part == 0) ? bq : (part == 1) ? bk : bv;
        g_bcat[n] = bb[m];
    }
}

// ---------------- round Wo|W1|W2 into g_wrnd (float4) -----------------------
#define WRND_TOTAL4 ((D_*D_ + D_*FF_ + FF_*D_) / 4)
__global__ __launch_bounds__(256) void wround_kernel(
    const float* __restrict__ Wo, const float* __restrict__ W1,
    const float* __restrict__ W2)
{
    int t = blockIdx.x * blockDim.x + threadIdx.x;
    if (t >= WRND_TOTAL4) return;
    int i4 = t << 2;
    const float* src;
    if (i4 < D_ * D_)                 src = Wo + i4;
    else if (i4 < D_ * D_ + D_ * FF_) src = W1 + (i4 - D_ * D_);
    else                              src = W2 + (i4 - D_ * D_ - D_ * FF_);
    float4 v = *(const float4*)src;
    float4 o = { rtf(v.x), rtf(v.y), rtf(v.z), rtf(v.w) };
    *(float4*)(g_wrnd + i4) = o;
}

// ---------------- layernorm (output tf32-rounded) ---------------------------
__global__ __launch_bounds__(256) void ln_kernel(
    const float* __restrict__ x, const float* __restrict__ g,
    const float* __restrict__ bta, float* __restrict__ y)
{
    int row = blockIdx.x;
    int tid = threadIdx.x;
    const float4* xr = (const float4*)(x + (size_t)row * D_);
    float4 v = xr[tid];
    float s  = v.x + v.y + v.z + v.w;
    float ss = v.x*v.x + v.y*v.y + v.z*v.z + v.w*v.w;
    __shared__ float sh_s[8], sh_ss[8];
    #pragma unroll
    for (int o = 16; o > 0; o >>= 1) {
        s  += __shfl_down_sync(0xffffffffu, s,  o);
        ss += __shfl_down_sync(0xffffffffu, ss, o);
    }
    if ((tid & 31) == 0) { sh_s[tid >> 5] = s; sh_ss[tid >> 5] = ss; }
    __syncthreads();
    float S = 0.f, SS = 0.f;
    #pragma unroll
    for (int i = 0; i < 8; i++) { S += sh_s[i]; SS += sh_ss[i]; }
    float mu  = S * (1.0f / D_);
    float var = SS * (1.0f / D_) - mu * mu;
    float inv = rsqrtf(var + 1e-5f);
    float4 g4 = ((const float4*)g)[tid];
    float4 b4 = ((const float4*)bta)[tid];
    float4 o;
    o.x = rtf((v.x - mu) * inv * g4.x + b4.x);
    o.y = rtf((v.y - mu) * inv * g4.y + b4.y);
    o.z = rtf((v.z - mu) * inv * g4.z + b4.z);
    o.w = rtf((v.w - mu) * inv * g4.w + b4.w);
    ((float4*)(y + (size_t)row * D_))[tid] = o;
}

// ---------------- tf32 tensor-core GEMM 128x128x16, cp.async 3-stage --------
// C[M,N] = A[M,K] * B[K,N] (row-major) + epilogue. A and B pre-rounded tf32.
// 3 smem stages, wait_group 1: tile i's load issued 2 iters ahead, tile i+1
// stays in flight during compute of tile i -> zero load-latency exposure.
// EPI bit0: +bias  bit1: gelu (rounds)  bit2: +res  bit3: round output
#define TG_AS (3*128*20)
#define TG_SMEM_BYTES ((TG_AS + 3*16*136) * 4)

template <int EPI>
__global__ __launch_bounds__(256, 2) void tgemm_kernel(
    const float* __restrict__ A, const float* __restrict__ Bm,
    float* __restrict__ C, const float* __restrict__ bias,
    const float* __restrict__ res, int M, int N, int K)
{
    extern __shared__ float dynsm[];
    float (*As)[128][20] = (float (*)[128][20])dynsm;
    float (*Bs)[16][136] = (float (*)[16][136])(dynsm + TG_AS);
    int tid = threadIdx.x;
    int lane = tid & 31, warp = tid >> 5;
    int g = lane >> 2, tg = lane & 3;
    int mw = (warp & 3) << 5;
    int nw = (warp >> 2) << 6;
    int bm = blockIdx.y, bn = blockIdx.x;
    const float* Ab = A  + (size_t)bm * 128 * K;
    const float* Bb = Bm + (size_t)bn * 128;

    float acc[2][8][4];
    #pragma unroll
    for (int mi = 0; mi < 2; mi++)
        #pragma unroll
        for (int j = 0; j < 8; j++)
            #pragma unroll
            for (int q = 0; q < 4; q++) acc[mi][j][q] = 0.f;

    int am  = tid >> 1;
    int ak  = (tid & 1) << 3;
    int bkr = tid >> 5;
    int bn4 = lane << 2;

    int nk = K >> 4;
    // prefetch tiles 0 and 1 (two separate groups)
    #pragma unroll
    for (int p = 0; p < 2; p++) {
        int kt = p << 4;
        cp_async16(&As[p][am][ak],       Ab + (size_t)am * K + kt + ak);
        cp_async16(&As[p][am][ak + 4],   Ab + (size_t)am * K + kt + ak + 4);
        cp_async16(&Bs[p][bkr][bn4],     Bb + (size_t)(kt + bkr) * N + bn4);
        cp_async16(&Bs[p][bkr + 8][bn4], Bb + (size_t)(kt + bkr + 8) * N + bn4);
        CP_COMMIT();
    }

    int sb = 0;   // stage of tile `it`
    int sp = 2;   // stage to prefetch into (tile it+2)
    for (int it = 0; it < nk; it++) {
        if (it + 1 < nk) { CP_WAIT1(); } else { CP_WAIT0(); }
        __syncthreads();
        if (it + 2 < nk) {
            int kt = (it + 2) << 4;
            cp_async16(&As[sp][am][ak],       Ab + (size_t)am * K + kt + ak);
            cp_async16(&As[sp][am][ak + 4],   Ab + (size_t)am * K + kt + ak + 4);
            cp_async16(&Bs[sp][bkr][bn4],     Bb + (size_t)(kt + bkr) * N + bn4);
            cp_async16(&Bs[sp][bkr + 8][bn4], Bb + (size_t)(kt + bkr + 8) * N + bn4);
            CP_COMMIT();
        }
        #pragma unroll
        for (int kk = 0; kk < 16; kk += 8) {
            uint32_t af[2][4], bf[8][2];
            #pragma unroll
            for (int mi = 0; mi < 2; mi++) {
                int r = mw + (mi << 4) + g;
                af[mi][0] = __float_as_uint(As[sb][r    ][kk + tg]);
                af[mi][1] = __float_as_uint(As[sb][r + 8][kk + tg]);
                af[mi][2] = __float_as_uint(As[sb][r    ][kk + tg + 4]);
                af[mi][3] = __float_as_uint(As[sb][r + 8][kk + tg + 4]);
            }
            #pragma unroll
            for (int j = 0; j < 8; j++) {
                bf[j][0] = __float_as_uint(Bs[sb][kk + tg    ][nw + (j << 3) + g]);
                bf[j][1] = __float_as_uint(Bs[sb][kk + tg + 4][nw + (j << 3) + g]);
            }
            #pragma unroll
            for (int mi = 0; mi < 2; mi++)
                #pragma unroll
                for (int j = 0; j < 8; j++)
                    mma_tf32(acc[mi][j], af[mi], bf[j]);
        }
        sb = (sb == 2) ? 0 : sb + 1;
        sp = (sp == 2) ? 0 : sp + 1;
    }

    #pragma unroll
    for (int mi = 0; mi < 2; mi++) {
        int r0 = bm * 128 + mw + (mi << 4) + g;
        int r1 = r0 + 8;
        #pragma unroll
        for (int j = 0; j < 8; j++) {
            int c = bn * 128 + nw + (j << 3) + (tg << 1);
            float v0 = acc[mi][j][0], v1 = acc[mi][j][1];
            float v2 = acc[mi][j][2], v3 = acc[mi][j][3];
            if (EPI & 1) {
                float2 bv = *(const float2*)(bias + c);
                v0 += bv.x; v1 += bv.y; v2 += bv.x; v3 += bv.y;
            }
            if (EPI & 2) {
                v0 = rtf(geluf(v0)); v1 = rtf(geluf(v1));
                v2 = rtf(geluf(v2)); v3 = rtf(geluf(v3));
            }
            if (EPI & 4) {
                float2 ra = *(const float2*)(res + (size_t)r0 * N + c);
                float2 rb = *(const float2*)(res + (size_t)r1 * N + c);
                v0 += ra.x; v1 += ra.y; v2 += rb.x; v3 += rb.y;
            }
            if (EPI & 8) {
                v0 = rtf(v0); v1 = rtf(v1); v2 = rtf(v2); v3 = rtf(v3);
            }
            float2 w0 = { v0, v1 }, w1 = { v2, v3 };
            *(float2*)(C + (size_t)r0 * N + c) = w0;
            *(float2*)(C + (size_t)r1 * N + c) = w1;
        }
    }
}

// ---------------- flash attention, tf32 tensor cores + cp.async K/V --------
#define QP 68
#define VP 72
#define FLASH_SMEM_FLOATS (64*QP + 2*64*QP + 2*64*VP + 64*QP + 256)
#define FLASH_SMEM_BYTES (FLASH_SMEM_FLOATS * 4)

__global__ __launch_bounds__(256, 2) void flash_attn_kernel()
{
    extern __shared__ uint32_t usm[];
    uint32_t* Qs = usm;                    // [64][QP]
    uint32_t* Ks = Qs + 64 * QP;           // [2][64][QP]
    uint32_t* Vs = Ks + 2 * 64 * QP;       // [2][64][VP]
    uint32_t* Ps = Vs + 2 * 64 * VP;       // [64][QP]
    float* redm  = (float*)(Ps + 64 * QP);
    float* reds  = redm + 128;

    int bh = blockIdx.y;
    int b = bh >> 4, h = bh & 15;
    int t0 = blockIdx.x * 64;
    int tid = threadIdx.x;
    int lane = tid & 31, warp = tid >> 5;
    int g = lane >> 2, tg = lane & 3;
    int wm = warp & 3, wn = warp >> 2;
    int m0r = (wm << 4) + g;
    int nb  = wn << 5;

    const float* qbase = g_qkv + ((size_t)b * T_) * TD3_ + h * 64;
    int lrow = tid >> 4;
    int le4  = (tid & 15) << 2;

    #pragma unroll
    for (int i = 0; i < 4; i++) {
        int row = lrow + i * 16;
        cp_async16(&Qs[row * QP + le4], qbase + (size_t)(t0 + row) * TD3_ + le4);
    }
    CP_COMMIT();
    #pragma unroll
    for (int i = 0; i < 4; i++) {
        int row = lrow + i * 16;
        cp_async16(&Ks[row * QP + le4], qbase + 1024 + (size_t)row * TD3_ + le4);
        cp_async16(&Vs[row * VP + le4], qbase + 2048 + (size_t)row * TD3_ + le4);
    }
    CP_COMMIT();

    float accO[4][4];
    #pragma unroll
    for (int j = 0; j < 4; j++)
        #pragma unroll
        for (int q = 0; q < 4; q++) accO[j][q] = 0.f;
    float m0 = -3.0e38f, m1 = -3.0e38f, l0 = 0.f, l1 = 0.f;

    for (int st = 0; st < 16; st++) {
        int buf = st & 1;
        uint32_t* Kb = Ks + buf * 64 * QP;
        uint32_t* Vb = Vs + buf * 64 * VP;
        CP_WAIT0();
        __syncthreads();
        if (st + 1 < 16) {
            int s1 = (st + 1) * 64;
            uint32_t* Kn = Ks + (buf ^ 1) * 64 * QP;
            uint32_t* Vn = Vs + (buf ^ 1) * 64 * VP;
            #pragma unroll
            for (int i = 0; i < 4; i++) {
                int row = lrow + i * 16;
                cp_async16(&Kn[row * QP + le4], qbase + 1024 + (size_t)(s1 + row) * TD3_ + le4);
                cp_async16(&Vn[row * VP + le4], qbase + 2048 + (size_t)(s1 + row) * TD3_ + le4);
            }
            CP_COMMIT();
        }

        float sacc[4][4];
        #pragma unroll
        for (int j = 0; j < 4; j++)
            #pragma unroll
            for (int q = 0; q < 4; q++) sacc[j][q] = 0.f;
        #pragma unroll
        for (int kk = 0; kk < 64; kk += 8) {
            uint32_t af[4], bf[4][2];
            af[0] = Qs[m0r * QP + kk + tg];
            af[1] = Qs[(m0r + 8) * QP + kk + tg];
            af[2] = Qs[m0r * QP + kk + tg + 4];
            af[3] = Qs[(m0r + 8) * QP + kk + tg + 4];
            #pragma unroll
            for (int j = 0; j < 4; j++) {
                int n = nb + (j << 3) + g;
                bf[j][0] = Kb[n * QP + kk + tg];
                bf[j][1] = Kb[n * QP + kk + tg + 4];
            }
            #pragma unroll
            for (int j = 0; j < 4; j++) mma_tf32(sacc[j], af, bf[j]);
        }

        float rmax0 = -3.0e38f, rmax1 = -3.0e38f;
        #pragma unroll
        for (int j = 0; j < 4; j++) {
            #pragma unroll
            for (int q = 0; q < 4; q++) sacc[j][q] *= 0.125f;
            rmax0 = fmaxf(rmax0, fmaxf(sacc[j][0], sacc[j][1]));
            rmax1 = fmaxf(rmax1, fmaxf(sacc[j][2], sacc[j][3]));
        }
        rmax0 = fmaxf(rmax0, __shfl_xor_sync(0xffffffffu, rmax0, 1));
        rmax0 = fmaxf(rmax0, __shfl_xor_sync(0xffffffffu, rmax0, 2));
        rmax1 = fmaxf(rmax1, __shfl_xor_sync(0xffffffffu, rmax1, 1));
        rmax1 = fmaxf(rmax1, __shfl_xor_sync(0xffffffffu, rmax1, 2));
        if (tg == 0) {
            redm[m0r * 2 + wn]       = rmax0;
            redm[(m0r + 8) * 2 + wn] = rmax1;
        }
        __syncthreads();
        float mn0 = fmaxf(m0, fmaxf(redm[m0r * 2], redm[m0r * 2 + 1]));
        float mn1 = fmaxf(m1, fmaxf(redm[(m0r + 8) * 2], redm[(m0r + 8) * 2 + 1]));
        float alpha0 = __expf(m0 - mn0);
        float alpha1 = __expf(m1 - mn1);
        m0 = mn0; m1 = mn1;

        float rs0 = 0.f, rs1 = 0.f;
        #pragma unroll
        for (int j = 0; j < 4; j++) {
            float p00 = __expf(sacc[j][0] - mn0);
            float p01 = __expf(sacc[j][1] - mn0);
            float p10 = __expf(sacc[j][2] - mn1);
            float p11 = __expf(sacc[j][3] - mn1);
            rs0 += p00 + p01; rs1 += p10 + p11;
            int col = nb + (j << 3) + (tg << 1);
            uint2 u0 = { f2tf(p00), f2tf(p01) };
            uint2 u1 = { f2tf(p10), f2tf(p11) };
            *(uint2*)&Ps[m0r * QP + col]       = u0;
            *(uint2*)&Ps[(m0r + 8) * QP + col] = u1;
        }
        rs0 += __shfl_xor_sync(0xffffffffu, rs0, 1);
        rs0 += __shfl_xor_sync(0xffffffffu, rs0, 2);
        rs1 += __shfl_xor_sync(0xffffffffu, rs1, 1);
        rs1 += __shfl_xor_sync(0xffffffffu, rs1, 2);
        if (tg == 0) {
            reds[m0r * 2 + wn]       = rs0;
            reds[(m0r + 8) * 2 + wn] = rs1;
        }
        #pragma unroll
        for (int j = 0; j < 4; j++) {
            accO[j][0] *= alpha0; accO[j][1] *= alpha0;
            accO[j][2] *= alpha1; accO[j][3] *= alpha1;
        }
        __syncthreads();
        l0 = l0 * alpha0 + reds[m0r * 2] + reds[m0r * 2 + 1];
        l1 = l1 * alpha1 + reds[(m0r + 8) * 2] + reds[(m0r + 8) * 2 + 1];

        #pragma unroll
        for (int kk = 0; kk < 64; kk += 8) {
            uint32_t af[4], bf[4][2];
            af[0] = Ps[m0r * QP + kk + tg];
            af[1] = Ps[(m0r + 8) * QP + kk + tg];
            af[2] = Ps[m0r * QP + kk + tg + 4];
            af[3] = Ps[(m0r + 8) * QP + kk + tg + 4];
            #pragma unroll
            for (int j = 0; j < 4; j++) {
                int n = nb + (j << 3) + g;
                bf[j][0] = Vb[(kk + tg) * VP + n];
                bf[j][1] = Vb[(kk + tg + 4) * VP + n];
            }
            #pragma unroll
            for (int j = 0; j < 4; j++) mma_tf32(accO[j], af, bf[j]);
        }
    }

    float inv0 = 1.0f / l0;
    float inv1 = 1.0f / l1;
    float* out0 = g_ctx + ((size_t)b * T_ + t0 + m0r) * D_ + h * 64;
    float* out1 = out0 + (size_t)8 * D_;
    #pragma unroll
    for (int j = 0; j < 4; j++) {
        int col = nb + (j << 3) + (tg << 1);
        float2 w0 = { rtf(accO[j][0] * inv0), rtf(accO[j][1] * inv0) };
        float2 w1 = { rtf(accO[j][2] * inv1), rtf(accO[j][3] * inv1) };
        *(float2*)(out0 + col) = w0;
        *(float2*)(out1 + col) = w1;
    }
}

// ---------------- launcher --------------------------------------------------
extern "C" void kernel_launch(void* const* d_in, const int* in_sizes, int n_in,
                              void* d_out, int out_size)
{
    const float* x    = (const float*)d_in[0];
    const float* ln1g = (const float*)d_in[1];
    const float* ln1b = (const float*)d_in[2];
    const float* ln2g = (const float*)d_in[3];
    const float* ln2b = (const float*)d_in[4];
    const float* Wq   = (const float*)d_in[5];
    const float* bq   = (const float*)d_in[6];
    const float* Wk   = (const float*)d_in[7];
    const float* bk   = (const float*)d_in[8];
    const float* Wv   = (const float*)d_in[9];
    const float* bv   = (const float*)d_in[10];
    const float* Wo   = (const float*)d_in[11];
    const float* bo   = (const float*)d_in[12];
    const float* W1   = (const float*)d_in[13];
    const float* b1   = (const float*)d_in[14];
    const float* W2   = (const float*)d_in[15];
    const float* b2   = (const float*)d_in[16];
    float* out = (float*)d_out;

    static float* h_    = nullptr;
    static float* qkv_  = nullptr;
    static float* wcat_ = nullptr;
    static float* bcat_ = nullptr;
    static float* ctx_  = nullptr;
    static float* ffa_  = nullptr;
    static float* wrnd_ = nullptr;
    if (!h_) {   // pointer cache only — identical work every call
        cudaGetSymbolAddress((void**)&h_,    g_h);
        cudaGetSymbolAddress((void**)&qkv_,  g_qkv);
        cudaGetSymbolAddress((void**)&wcat_, g_wcat);
        cudaGetSymbolAddress((void**)&bcat_, g_bcat);
        cudaGetSymbolAddress((void**)&ctx_,  g_ctx);
        cudaGetSymbolAddress((void**)&ffa_,  g_ffa);
        cudaGetSymbolAddress((void**)&wrnd_, g_wrnd);
        cudaFuncSetAttribute(flash_attn_kernel,
                             cudaFuncAttributeMaxDynamicSharedMemorySize,
                             FLASH_SMEM_BYTES);
        cudaFuncSetAttribute(tgemm_kernel<9>,
                             cudaFuncAttributeMaxDynamicSharedMemorySize, TG_SMEM_BYTES);
        cudaFuncSetAttribute(tgemm_kernel<5>,
                             cudaFuncAttributeMaxDynamicSharedMemorySize, TG_SMEM_BYTES);
        cudaFuncSetAttribute(tgemm_kernel<3>,
                             cudaFuncAttributeMaxDynamicSharedMemorySize, TG_SMEM_BYTES);
    }
    float* wo_r = wrnd_;
    float* w1_r = wrnd_ + (size_t)D_ * D_;
    float* w2_r = wrnd_ + (size_t)D_ * D_ + (size_t)D_ * FF_;

    // 1) weight prep (rounded)
    repack_kernel<<<(D_ * TD3_ + 255) / 256, 256>>>(Wq, Wk, Wv, bq, bk, bv);
    wround_kernel<<<(WRND_TOTAL4 + 255) / 256, 256>>>(Wo, W1, W2);
    // 2) ln1
    ln_kernel<<<BT_, 256>>>(x, ln1g, ln1b, h_);
    // 3) QKV = h @ Wcat + bcat (rounded output for flash)
    tgemm_kernel<9><<<dim3(TD3_ / 128, BT_ / 128), 256, TG_SMEM_BYTES>>>(
        h_, wcat_, qkv_, bcat_, nullptr, BT_, TD3_, D_);
    // 4-6) fused attention -> g_ctx (rounded)
    flash_attn_kernel<<<dim3(16, B_ * H_), 256, FLASH_SMEM_BYTES>>>();
    // 7) X1 = x + ctx @ Wo + bo
    tgemm_kernel<5><<<dim3(D_ / 128, BT_ / 128), 256, TG_SMEM_BYTES>>>(
        ctx_, wo_r, out, bo, x, BT_, D_, D_);
    // 8) ln2
    ln_kernel<<<BT_, 256>>>(out, ln2g, ln2b, h_);
    // 9) ffa = gelu(h @ W1 + b1)
    tgemm_kernel<3><<<dim3(FF_ / 128, BT_ / 128), 256, TG_SMEM_BYTES>>>(
        h_, w1_r, ffa_, b1, nullptr, BT_, FF_, D_);
    // 10) out = X1 + ffa @ W2 + b2
    tgemm_kernel<5><<<dim3(D_ / 128, BT_ / 128), 256, TG_SMEM_BYTES>>>(
        ffa_, w2_r, out, b2, out, BT_, D_, FF_);
}

// round 12
// speedup vs baseline: 1.4689x; 1.4689x over previous
#include <cuda_runtime.h>
#include <cuda_fp16.h>
#include <cstdint>
#include <cstddef>

#define B_  8
#define T_  1024
#define D_  1024
#define H_  16
#define HD_ 64
#define FF_ 4096
#define BT_ (B_*T_)            // 8192
#define TD3_ (3*D_)            // 3072

// ---------------- scratch (device globals: allocation-guard-safe) ----------
__device__ __half g_h[(size_t)BT_ * D_];         // 16 MB (ln output, half)
__device__ float  g_qkv[(size_t)BT_ * TD3_];     // 96 MB (tf32-rounded fp32)
__device__ float  g_wcat[(size_t)D_ * TD3_];     // 12 MB (staging fp32)
__device__ __half g_wcatT[(size_t)TD3_ * D_];    // 6 MB  [N][K] half
__device__ float  g_bcat[TD3_];
__device__ __half g_ctx[(size_t)BT_ * D_];       // 16 MB (flash out, half)
__device__ __half g_ffa[(size_t)BT_ * FF_];      // 64 MB (gelu out, half)
__device__ __half g_wrndh[(size_t)D_*D_ + (size_t)D_*FF_ + (size_t)FF_*D_]; // 18 MB

// ---------------- helpers ---------------------------------------------------
__device__ __forceinline__ float geluf(float x) {
    return 0.5f * x * (1.0f + erff(x * 0.70710678118654752f));
}
__device__ __forceinline__ uint32_t f2tf(float x) {
    uint32_t r; asm("cvt.rna.tf32.f32 %0, %1;" : "=r"(r) : "f"(x)); return r;
}
__device__ __forceinline__ float rtf(float x) {
    return __uint_as_float(f2tf(x));
}
__device__ __forceinline__ void mma_tf32(float c[4], const uint32_t a[4], const uint32_t b[2]) {
    asm volatile(
        "mma.sync.aligned.m16n8k8.row.col.f32.tf32.tf32.f32 "
        "{%0,%1,%2,%3}, {%4,%5,%6,%7}, {%8,%9}, {%0,%1,%2,%3};"
        : "+f"(c[0]), "+f"(c[1]), "+f"(c[2]), "+f"(c[3])
        : "r"(a[0]), "r"(a[1]), "r"(a[2]), "r"(a[3]), "r"(b[0]), "r"(b[1]));
}
__device__ __forceinline__ void mma_f16(float c[4], const uint32_t a[4], const uint32_t b[2]) {
    asm volatile(
        "mma.sync.aligned.m16n8k16.row.col.f32.f16.f16.f32 "
        "{%0,%1,%2,%3}, {%4,%5,%6,%7}, {%8,%9}, {%0,%1,%2,%3};"
        : "+f"(c[0]), "+f"(c[1]), "+f"(c[2]), "+f"(c[3])
        : "r"(a[0]), "r"(a[1]), "r"(a[2]), "r"(a[3]), "r"(b[0]), "r"(b[1]));
}
__device__ __forceinline__ void cp_async16(void* sptr, const void* gptr) {
    uint32_t s = (uint32_t)__cvta_generic_to_shared(sptr);
    asm volatile("cp.async.cg.shared.global [%0], [%1], 16;" :: "r"(s), "l"(gptr));
}
#define CP_COMMIT() asm volatile("cp.async.commit_group;")
#define CP_WAIT0()  asm volatile("cp.async.wait_group 0;")

// ---------------- weight repack: Wq/Wk/Wv [H,D,HD] -> Wcat fp32 [D, 3D] -----
__global__ __launch_bounds__(256) void repack_kernel(
    const float* __restrict__ Wq, const float* __restrict__ Wk, const float* __restrict__ Wv,
    const float* __restrict__ bq, const float* __restrict__ bk, const float* __restrict__ bv)
{
    int t = blockIdx.x * blockDim.x + threadIdx.x;
    if (t >= D_ * TD3_) return;
    int d = t / TD3_;
    int n = t - d * TD3_;
    int part = n >> 10;
    int m = n & (D_ - 1);
    int h = m >> 6, e = m & 63;
    const float* W = (part == 0) ? Wq : (part == 1) ? Wk : Wv;
    g_wcat[t] = W[((size_t)h * D_ + d) * HD_ + e];
    if (d == 0) {
        const float* bb = (part == 0) ? bq : (part == 1) ? bk : bv;
        g_bcat[n] = bb[m];
    }
}

// ---------------- tiled transpose fp32[R][C] -> half[C][R] ------------------
__global__ __launch_bounds__(256) void transTh_kernel(
    const float* __restrict__ src, __half* __restrict__ dst, int R, int C)
{
    __shared__ float tile[32][33];
    int bx = blockIdx.x * 32, by = blockIdx.y * 32;
    int tx = threadIdx.x & 31, ty = threadIdx.x >> 5;   // 32 x 8
    #pragma unroll
    for (int i = 0; i < 32; i += 8)
        tile[ty + i][tx] = src[(size_t)(by + ty + i) * C + bx + tx];
    __syncthreads();
    #pragma unroll
    for (int i = 0; i < 32; i += 8)
        dst[(size_t)(bx + ty + i) * R + by + tx] = __float2half(tile[tx][ty + i]);
}

// ---------------- layernorm: fp32 in -> half out ----------------------------
__global__ __launch_bounds__(256) void ln_kernel(
    const float* __restrict__ x, const float* __restrict__ g,
    const float* __restrict__ bta, __half* __restrict__ y)
{
    int row = blockIdx.x;
    int tid = threadIdx.x;
    const float4* xr = (const float4*)(x + (size_t)row * D_);
    float4 v = xr[tid];
    float s  = v.x + v.y + v.z + v.w;
    float ss = v.x*v.x + v.y*v.y + v.z*v.z + v.w*v.w;
    __shared__ float sh_s[8], sh_ss[8];
    #pragma unroll
    for (int o = 16; o > 0; o >>= 1) {
        s  += __shfl_down_sync(0xffffffffu, s,  o);
        ss += __shfl_down_sync(0xffffffffu, ss, o);
    }
    if ((tid & 31) == 0) { sh_s[tid >> 5] = s; sh_ss[tid >> 5] = ss; }
    __syncthreads();
    float S = 0.f, SS = 0.f;
    #pragma unroll
    for (int i = 0; i < 8; i++) { S += sh_s[i]; SS += sh_ss[i]; }
    float mu  = S * (1.0f / D_);
    float var = SS * (1.0f / D_) - mu * mu;
    float inv = rsqrtf(var + 1e-5f);
    float4 g4 = ((const float4*)g)[tid];
    float4 b4 = ((const float4*)bta)[tid];
    __half2 o0 = __floats2half2_rn((v.x - mu) * inv * g4.x + b4.x,
                                   (v.y - mu) * inv * g4.y + b4.y);
    __half2 o1 = __floats2half2_rn((v.z - mu) * inv * g4.z + b4.z,
                                   (v.w - mu) * inv * g4.w + b4.w);
    __half2* yp = (__half2*)(y + (size_t)row * D_) + tid * 2;
    yp[0] = o0; yp[1] = o1;
}

// ---------------- fp16 tensor-core GEMM 128x128, K-stage 32, 2-stage --------
// C[M,N] = A[M,K] (half, row-major) * Bt[N,K] (half) + epilogue (fp32 accum)
// EPI bit0: +bias  bit1: gelu  bit2: +res(fp32)  bit3: tf32-round fp32 out
// OUTH: 1 -> C is __half*, 0 -> C is float*
template <int EPI, int OUTH>
__global__ __launch_bounds__(256, 2) void hgemm_kernel(
    const __half* __restrict__ A, const __half* __restrict__ Bt,
    void* __restrict__ Cv, const float* __restrict__ bias,
    const float* __restrict__ res, int M, int N, int K)
{
    __shared__ uint32_t As[2][128][20];   // [m][k2], cols 0..15 used
    __shared__ uint32_t Bs[2][128][20];   // [n][k2]
    int tid = threadIdx.x;
    int lane = tid & 31, warp = tid >> 5;
    int g = lane >> 2, tg = lane & 3;
    int mw = (warp & 3) << 5;
    int nw = (warp >> 2) << 6;
    int bm = blockIdx.y, bn = blockIdx.x;
    const __half* Ab = A  + (size_t)bm * 128 * K;
    const __half* Bb = Bt + (size_t)bn * 128 * K;

    float acc[2][8][4];
    #pragma unroll
    for (int mi = 0; mi < 2; mi++)
        #pragma unroll
        for (int j = 0; j < 8; j++)
            #pragma unroll
            for (int q = 0; q < 4; q++) acc[mi][j][q] = 0.f;

    int lrow = tid >> 1;            // 0..127
    int lseg = (tid & 1) << 3;      // uint32 offset 0 or 8 (16 halves)

    // prefetch stage 0
    cp_async16(&As[0][lrow][lseg],     Ab + (size_t)lrow * K + (lseg << 1));
    cp_async16(&As[0][lrow][lseg + 4], Ab + (size_t)lrow * K + (lseg << 1) + 8);
    cp_async16(&Bs[0][lrow][lseg],     Bb + (size_t)lrow * K + (lseg << 1));
    cp_async16(&Bs[0][lrow][lseg + 4], Bb + (size_t)lrow * K + (lseg << 1) + 8);
    CP_COMMIT();

    int nk = K >> 5;
    for (int it = 0; it < nk; it++) {
        int buf = it & 1;
        CP_WAIT0();
        __syncthreads();
        if (it + 1 < nk) {
            int kt = (it + 1) << 5;
            int nb2 = buf ^ 1;
            cp_async16(&As[nb2][lrow][lseg],     Ab + (size_t)lrow * K + kt + (lseg << 1));
            cp_async16(&As[nb2][lrow][lseg + 4], Ab + (size_t)lrow * K + kt + (lseg << 1) + 8);
            cp_async16(&Bs[nb2][lrow][lseg],     Bb + (size_t)lrow * K + kt + (lseg << 1));
            cp_async16(&Bs[nb2][lrow][lseg + 4], Bb + (size_t)lrow * K + kt + (lseg << 1) + 8);
            CP_COMMIT();
        }
        #pragma unroll
        for (int ks = 0; ks < 2; ks++) {      // two k16 steps
            int k2b = ks << 3;
            uint32_t af[2][4], bf[8][2];
            #pragma unroll
            for (int mi = 0; mi < 2; mi++) {
                int r = mw + (mi << 4) + g;
                af[mi][0] = As[buf][r    ][k2b + tg];
                af[mi][1] = As[buf][r + 8][k2b + tg];
                af[mi][2] = As[buf][r    ][k2b + 4 + tg];
                af[mi][3] = As[buf][r + 8][k2b + 4 + tg];
            }
            #pragma unroll
            for (int j = 0; j < 8; j++) {
                int n = nw + (j << 3) + g;
                bf[j][0] = Bs[buf][n][k2b + tg];
                bf[j][1] = Bs[buf][n][k2b + 4 + tg];
            }
            #pragma unroll
            for (int mi = 0; mi < 2; mi++)
                #pragma unroll
                for (int j = 0; j < 8; j++)
                    mma_f16(acc[mi][j], af[mi], bf[j]);
        }
    }

    #pragma unroll
    for (int mi = 0; mi < 2; mi++) {
        int r0 = bm * 128 + mw + (mi << 4) + g;
        int r1 = r0 + 8;
        #pragma unroll
        for (int j = 0; j < 8; j++) {
            int c = bn * 128 + nw + (j << 3) + (tg << 1);
            float v0 = acc[mi][j][0], v1 = acc[mi][j][1];
            float v2 = acc[mi][j][2], v3 = acc[mi][j][3];
            if (EPI & 1) {
                float2 bv = *(const float2*)(bias + c);
                v0 += bv.x; v1 += bv.y; v2 += bv.x; v3 += bv.y;
            }
            if (EPI & 2) {
                v0 = geluf(v0); v1 = geluf(v1);
                v2 = geluf(v2); v3 = geluf(v3);
            }
            if (EPI & 4) {
                float2 ra = *(const float2*)(res + (size_t)r0 * N + c);
                float2 rb = *(const float2*)(res + (size_t)r1 * N + c);
                v0 += ra.x; v1 += ra.y; v2 += rb.x; v3 += rb.y;
            }
            if (OUTH) {
                __half* Ch = (__half*)Cv;
                *(__half2*)(Ch + (size_t)r0 * N + c) = __floats2half2_rn(v0, v1);
                *(__half2*)(Ch + (size_t)r1 * N + c) = __floats2half2_rn(v2, v3);
            } else {
                float* Cf = (float*)Cv;
                if (EPI & 8) { v0 = rtf(v0); v1 = rtf(v1); v2 = rtf(v2); v3 = rtf(v3); }
                float2 w0 = { v0, v1 }, w1 = { v2, v3 };
                *(float2*)(Cf + (size_t)r0 * N + c) = w0;
                *(float2*)(Cf + (size_t)r1 * N + c) = w1;
            }
        }
    }
}

// ---------------- flash attention, tf32 mma + cp.async K/V ------------------
// Unchanged numerics vs R9 (reads fp32 tf32-rounded qkv); epilogue now writes
// half ctx for the fp16 Wo GEMM.
#define QP 68
#define VP 72
#define FLASH_SMEM_FLOATS (64*QP + 2*64*QP + 2*64*VP + 64*QP + 256)
#define FLASH_SMEM_BYTES (FLASH_SMEM_FLOATS * 4)

__global__ __launch_bounds__(256, 2) void flash_attn_kernel()
{
    extern __shared__ uint32_t usm[];
    uint32_t* Qs = usm;
    uint32_t* Ks = Qs + 64 * QP;
    uint32_t* Vs = Ks + 2 * 64 * QP;
    uint32_t* Ps = Vs + 2 * 64 * VP;
    float* redm  = (float*)(Ps + 64 * QP);
    float* reds  = redm + 128;

    int bh = blockIdx.y;
    int b = bh >> 4, h = bh & 15;
    int t0 = blockIdx.x * 64;
    int tid = threadIdx.x;
    int lane = tid & 31, warp = tid >> 5;
    int g = lane >> 2, tg = lane & 3;
    int wm = warp & 3, wn = warp >> 2;
    int m0r = (wm << 4) + g;
    int nb  = wn << 5;

    const float* qbase = g_qkv + ((size_t)b * T_) * TD3_ + h * 64;
    int lrow = tid >> 4;
    int le4  = (tid & 15) << 2;

    #pragma unroll
    for (int i = 0; i < 4; i++) {
        int row = lrow + i * 16;
        cp_async16(&Qs[row * QP + le4], qbase + (size_t)(t0 + row) * TD3_ + le4);
    }
    CP_COMMIT();
    #pragma unroll
    for (int i = 0; i < 4; i++) {
        int row = lrow + i * 16;
        cp_async16(&Ks[row * QP + le4], qbase + 1024 + (size_t)row * TD3_ + le4);
        cp_async16(&Vs[row * VP + le4], qbase + 2048 + (size_t)row * TD3_ + le4);
    }
    CP_COMMIT();

    float accO[4][4];
    #pragma unroll
    for (int j = 0; j < 4; j++)
        #pragma unroll
        for (int q = 0; q < 4; q++) accO[j][q] = 0.f;
    float m0 = -3.0e38f, m1 = -3.0e38f, l0 = 0.f, l1 = 0.f;

    for (int st = 0; st < 16; st++) {
        int buf = st & 1;
        uint32_t* Kb = Ks + buf * 64 * QP;
        uint32_t* Vb = Vs + buf * 64 * VP;
        CP_WAIT0();
        __syncthreads();
        if (st + 1 < 16) {
            int s1 = (st + 1) * 64;
            uint32_t* Kn = Ks + (buf ^ 1) * 64 * QP;
            uint32_t* Vn = Vs + (buf ^ 1) * 64 * VP;
            #pragma unroll
            for (int i = 0; i < 4; i++) {
                int row = lrow + i * 16;
                cp_async16(&Kn[row * QP + le4], qbase + 1024 + (size_t)(s1 + row) * TD3_ + le4);
                cp_async16(&Vn[row * VP + le4], qbase + 2048 + (size_t)(s1 + row) * TD3_ + le4);
            }
            CP_COMMIT();
        }

        float sacc[4][4];
        #pragma unroll
        for (int j = 0; j < 4; j++)
            #pragma unroll
            for (int q = 0; q < 4; q++) sacc[j][q] = 0.f;
        #pragma unroll
        for (int kk = 0; kk < 64; kk += 8) {
            uint32_t af[4], bf[4][2];
            af[0] = Qs[m0r * QP + kk + tg];
            af[1] = Qs[(m0r + 8) * QP + kk + tg];
            af[2] = Qs[m0r * QP + kk + tg + 4];
            af[3] = Qs[(m0r + 8) * QP + kk + tg + 4];
            #pragma unroll
            for (int j = 0; j < 4; j++) {
                int n = nb + (j << 3) + g;
                bf[j][0] = Kb[n * QP + kk + tg];
                bf[j][1] = Kb[n * QP + kk + tg + 4];
            }
            #pragma unroll
            for (int j = 0; j < 4; j++) mma_tf32(sacc[j], af, bf[j]);
        }

        float rmax0 = -3.0e38f, rmax1 = -3.0e38f;
        #pragma unroll
        for (int j = 0; j < 4; j++) {
            #pragma unroll
            for (int q = 0; q < 4; q++) sacc[j][q] *= 0.125f;
            rmax0 = fmaxf(rmax0, fmaxf(sacc[j][0], sacc[j][1]));
            rmax1 = fmaxf(rmax1, fmaxf(sacc[j][2], sacc[j][3]));
        }
        rmax0 = fmaxf(rmax0, __shfl_xor_sync(0xffffffffu, rmax0, 1));
        rmax0 = fmaxf(rmax0, __shfl_xor_sync(0xffffffffu, rmax0, 2));
        rmax1 = fmaxf(rmax1, __shfl_xor_sync(0xffffffffu, rmax1, 1));
        rmax1 = fmaxf(rmax1, __shfl_xor_sync(0xffffffffu, rmax1, 2));
        if (tg == 0) {
            redm[m0r * 2 + wn]       = rmax0;
            redm[(m0r + 8) * 2 + wn] = rmax1;
        }
        __syncthreads();
        float mn0 = fmaxf(m0, fmaxf(redm[m0r * 2], redm[m0r * 2 + 1]));
        float mn1 = fmaxf(m1, fmaxf(redm[(m0r + 8) * 2], redm[(m0r + 8) * 2 + 1]));
        float alpha0 = __expf(m0 - mn0);
        float alpha1 = __expf(m1 - mn1);
        m0 = mn0; m1 = mn1;

        float rs0 = 0.f, rs1 = 0.f;
        #pragma unroll
        for (int j = 0; j < 4; j++) {
            float p00 = __expf(sacc[j][0] - mn0);
            float p01 = __expf(sacc[j][1] - mn0);
            float p10 = __expf(sacc[j][2] - mn1);
            float p11 = __expf(sacc[j][3] - mn1);
            rs0 += p00 + p01; rs1 += p10 + p11;
            int col = nb + (j << 3) + (tg << 1);
            uint2 u0 = { f2tf(p00), f2tf(p01) };
            uint2 u1 = { f2tf(p10), f2tf(p11) };
            *(uint2*)&Ps[m0r * QP + col]       = u0;
            *(uint2*)&Ps[(m0r + 8) * QP + col] = u1;
        }
        rs0 += __shfl_xor_sync(0xffffffffu, rs0, 1);
        rs0 += __shfl_xor_sync(0xffffffffu, rs0, 2);
        rs1 += __shfl_xor_sync(0xffffffffu, rs1, 1);
        rs1 += __shfl_xor_sync(0xffffffffu, rs1, 2);
        if (tg == 0) {
            reds[m0r * 2 + wn]       = rs0;
            reds[(m0r + 8) * 2 + wn] = rs1;
        }
        #pragma unroll
        for (int j = 0; j < 4; j++) {
            accO[j][0] *= alpha0; accO[j][1] *= alpha0;
            accO[j][2] *= alpha1; accO[j][3] *= alpha1;
        }
        __syncthreads();
        l0 = l0 * alpha0 + reds[m0r * 2] + reds[m0r * 2 + 1];
        l1 = l1 * alpha1 + reds[(m0r + 8) * 2] + reds[(m0r + 8) * 2 + 1];

        #pragma unroll
        for (int kk = 0; kk < 64; kk += 8) {
            uint32_t af[4], bf[4][2];
            af[0] = Ps[m0r * QP + kk + tg];
            af[1] = Ps[(m0r + 8) * QP + kk + tg];
            af[2] = Ps[m0r * QP + kk + tg + 4];
            af[3] = Ps[(m0r + 8) * QP + kk + tg + 4];
            #pragma unroll
            for (int j = 0; j < 4; j++) {
                int n = nb + (j << 3) + g;
                bf[j][0] = Vb[(kk + tg) * VP + n];
                bf[j][1] = Vb[(kk + tg + 4) * VP + n];
            }
            #pragma unroll
            for (int j = 0; j < 4; j++) mma_tf32(accO[j], af, bf[j]);
        }
    }

    float inv0 = 1.0f / l0;
    float inv1 = 1.0f / l1;
    __half* out0 = g_ctx + ((size_t)b * T_ + t0 + m0r) * D_ + h * 64;
    __half* out1 = out0 + (size_t)8 * D_;
    #pragma unroll
    for (int j = 0; j < 4; j++) {
        int col = nb + (j << 3) + (tg << 1);
        *(__half2*)(out0 + col) = __floats2half2_rn(accO[j][0] * inv0, accO[j][1] * inv0);
        *(__half2*)(out1 + col) = __floats2half2_rn(accO[j][2] * inv1, accO[j][3] * inv1);
    }
}

// ---------------- launcher --------------------------------------------------
extern "C" void kernel_launch(void* const* d_in, const int* in_sizes, int n_in,
                              void* d_out, int out_size)
{
    const float* x    = (const float*)d_in[0];
    const float* ln1g = (const float*)d_in[1];
    const float* ln1b = (const float*)d_in[2];
    const float* ln2g = (const float*)d_in[3];
    const float* ln2b = (const float*)d_in[4];
    const float* Wq   = (const float*)d_in[5];
    const float* bq   = (const float*)d_in[6];
    const float* Wk   = (const float*)d_in[7];
    const float* bk   = (const float*)d_in[8];
    const float* Wv   = (const float*)d_in[9];
    const float* bv   = (const float*)d_in[10];
    const float* Wo   = (const float*)d_in[11];
    const float* bo   = (const float*)d_in[12];
    const float* W1   = (const float*)d_in[13];
    const float* b1   = (const float*)d_in[14];
    const float* W2   = (const float*)d_in[15];
    const float* b2   = (const float*)d_in[16];
    float* out = (float*)d_out;

    static __half* h_     = nullptr;
    static float*  qkv_   = nullptr;
    static float*  wcat_  = nullptr;
    static __half* wcatT_ = nullptr;
    static float*  bcat_  = nullptr;
    static __half* ctx_   = nullptr;
    static __half* ffa_   = nullptr;
    static __half* wrnd_  = nullptr;
    if (!h_) {   // pointer cache only — identical work every call
        cudaGetSymbolAddress((void**)&h_,     g_h);
        cudaGetSymbolAddress((void**)&qkv_,   g_qkv);
        cudaGetSymbolAddress((void**)&wcat_,  g_wcat);
        cudaGetSymbolAddress((void**)&wcatT_, g_wcatT);
        cudaGetSymbolAddress((void**)&bcat_,  g_bcat);
        cudaGetSymbolAddress((void**)&ctx_,   g_ctx);
        cudaGetSymbolAddress((void**)&ffa_,   g_ffa);
        cudaGetSymbolAddress((void**)&wrnd_,  g_wrndh);
        cudaFuncSetAttribute(flash_attn_kernel,
                             cudaFuncAttributeMaxDynamicSharedMemorySize, FLASH_SMEM_BYTES);
    }
    __half* woT = wrnd_;
    __half* w1T = wrnd_ + (size_t)D_ * D_;
    __half* w2T = wrnd_ + (size_t)D_ * D_ + (size_t)D_ * FF_;

    // 1) weight prep: repack, then transpose+halve everything to [N][K]
    repack_kernel<<<(D_ * TD3_ + 255) / 256, 256>>>(Wq, Wk, Wv, bq, bk, bv);
    transTh_kernel<<<dim3(TD3_ / 32, D_ / 32), 256>>>(wcat_, wcatT_, D_, TD3_);
    transTh_kernel<<<dim3(D_ / 32, D_ / 32), 256>>>(Wo, woT, D_, D_);
    transTh_kernel<<<dim3(FF_ / 32, D_ / 32), 256>>>(W1, w1T, D_, FF_);
    transTh_kernel<<<dim3(D_ / 32, FF_ / 32), 256>>>(W2, w2T, FF_, D_);
    // 2) ln1 -> h (half)
    ln_kernel<<<BT_, 256>>>(x, ln1g, ln1b, h_);
    // 3) QKV = h @ Wcat + bcat -> fp32 tf32-rounded (flash input unchanged)
    hgemm_kernel<9, 0><<<dim3(TD3_ / 128, BT_ / 128), 256>>>(
        h_, wcatT_, qkv_, bcat_, nullptr, BT_, TD3_, D_);
    // 4-6) fused attention -> ctx (half)
    flash_attn_kernel<<<dim3(16, B_ * H_), 256, FLASH_SMEM_BYTES>>>();
    // 7) X1 = x + ctx @ Wo + bo -> out (fp32)
    hgemm_kernel<5, 0><<<dim3(D_ / 128, BT_ / 128), 256>>>(
        ctx_, woT, out, bo, x, BT_, D_, D_);
    // 8) ln2 -> h (half)
    ln_kernel<<<BT_, 256>>>(out, ln2g, ln2b, h_);
    // 9) ffa = gelu(h @ W1 + b1) -> half
    hgemm_kernel<3, 1><<<dim3(FF_ / 128, BT_ / 128), 256>>>(
        h_, w1T, ffa_, b1, nullptr, BT_, FF_, D_);
    // 10) out = X1 + ffa @ W2 + b2 -> fp32
    hgemm_kernel<5, 0><<<dim3(D_ / 128, BT_ / 128), 256>>>(
        ffa_, w2T, out, b2, out, BT_, D_, FF_);
}

// round 14
// speedup vs baseline: 1.6323x; 1.1113x over previous
#include <cuda_runtime.h>
#include <cuda_fp16.h>
#include <cstdint>
#include <cstddef>
#include <cstring>

#define B_  8
#define T_  1024
#define D_  1024
#define H_  16
#define HD_ 64
#define FF_ 4096
#define BT_ (B_*T_)            // 8192
#define TD3_ (3*D_)            // 3072

// ---------------- scratch (device globals: allocation-guard-safe) ----------
__device__ __half g_h[(size_t)BT_ * D_];         // 16 MB (ln output, half)
__device__ __half g_qkv[(size_t)BT_ * TD3_];     // 48 MB (QKV, half)
__device__ float  g_wcat[(size_t)D_ * TD3_];     // 12 MB (staging fp32)
__device__ __half g_wcatT[(size_t)TD3_ * D_];    // 6 MB  [N][K] half
__device__ float  g_bcat[TD3_];
__device__ __half g_ctx[(size_t)BT_ * D_];       // 16 MB (flash out, half)
__device__ __half g_ffa[(size_t)BT_ * FF_];      // 64 MB (gelu out, half)
__device__ __half g_wrndh[(size_t)D_*D_ + (size_t)D_*FF_ + (size_t)FF_*D_]; // 18 MB

// ---------------- helpers ---------------------------------------------------
__device__ __forceinline__ float geluf(float x) {
    return 0.5f * x * (1.0f + erff(x * 0.70710678118654752f));
}
__device__ __forceinline__ uint32_t h2u(__half2 v) {
    uint32_t r; memcpy(&r, &v, 4); return r;
}
__device__ __forceinline__ void mma_f16(float c[4], const uint32_t a[4], const uint32_t b[2]) {
    asm volatile(
        "mma.sync.aligned.m16n8k16.row.col.f32.f16.f16.f32 "
        "{%0,%1,%2,%3}, {%4,%5,%6,%7}, {%8,%9}, {%0,%1,%2,%3};"
        : "+f"(c[0]), "+f"(c[1]), "+f"(c[2]), "+f"(c[3])
        : "r"(a[0]), "r"(a[1]), "r"(a[2]), "r"(a[3]), "r"(b[0]), "r"(b[1]));
}
__device__ __forceinline__ void ldmatrix_x2_trans(uint32_t& r0, uint32_t& r1, uint32_t saddr) {
    asm volatile("ldmatrix.sync.aligned.m8n8.x2.trans.shared.b16 {%0, %1}, [%2];"
                 : "=r"(r0), "=r"(r1) : "r"(saddr));
}
__device__ __forceinline__ void cp_async16(void* sptr, const void* gptr) {
    uint32_t s = (uint32_t)__cvta_generic_to_shared(sptr);
    asm volatile("cp.async.cg.shared.global [%0], [%1], 16;" :: "r"(s), "l"(gptr));
}
#define CP_COMMIT() asm volatile("cp.async.commit_group;")
#define CP_WAIT0()  asm volatile("cp.async.wait_group 0;")

// ---------------- weight repack: Wq/Wk/Wv [H,D,HD] -> Wcat fp32 [D, 3D] -----
__global__ __launch_bounds__(256) void repack_kernel(
    const float* __restrict__ Wq, const float* __restrict__ Wk, const float* __restrict__ Wv,
    const float* __restrict__ bq, const float* __restrict__ bk, const float* __restrict__ bv)
{
    int t = blockIdx.x * blockDim.x + threadIdx.x;
    if (t >= D_ * TD3_) return;
    int d = t / TD3_;
    int n = t - d * TD3_;
    int part = n >> 10;
    int m = n & (D_ - 1);
    int h = m >> 6, e = m & 63;
    const float* W = (part == 0) ? Wq : (part == 1) ? Wk : Wv;
    g_wcat[t] = W[((size_t)h * D_ + d) * HD_ + e];
    if (d == 0) {
        const float* bb = (part == 0) ? bq : (part == 1) ? bk : bv;
        g_bcat[n] = bb[m];
    }
}

// ---------------- tiled transpose fp32[R][C] -> half[C][R] ------------------
__global__ __launch_bounds__(256) void transTh_kernel(
    const float* __restrict__ src, __half* __restrict__ dst, int R, int C)
{
    __shared__ float tile[32][33];
    int bx = blockIdx.x * 32, by = blockIdx.y * 32;
    int tx = threadIdx.x & 31, ty = threadIdx.x >> 5;   // 32 x 8
    #pragma unroll
    for (int i = 0; i < 32; i += 8)
        tile[ty + i][tx] = src[(size_t)(by + ty + i) * C + bx + tx];
    __syncthreads();
    #pragma unroll
    for (int i = 0; i < 32; i += 8)
        dst[(size_t)(bx + ty + i) * R + by + tx] = __float2half(tile[tx][ty + i]);
}

// ---------------- layernorm: fp32 in -> half out ----------------------------
__global__ __launch_bounds__(256) void ln_kernel(
    const float* __restrict__ x, const float* __restrict__ g,
    const float* __restrict__ bta, __half* __restrict__ y)
{
    int row = blockIdx.x;
    int tid = threadIdx.x;
    const float4* xr = (const float4*)(x + (size_t)row * D_);
    float4 v = xr[tid];
    float s  = v.x + v.y + v.z + v.w;
    float ss = v.x*v.x + v.y*v.y + v.z*v.z + v.w*v.w;
    __shared__ float sh_s[8], sh_ss[8];
    #pragma unroll
    for (int o = 16; o > 0; o >>= 1) {
        s  += __shfl_down_sync(0xffffffffu, s,  o);
        ss += __shfl_down_sync(0xffffffffu, ss, o);
    }
    if ((tid & 31) == 0) { sh_s[tid >> 5] = s; sh_ss[tid >> 5] = ss; }
    __syncthreads();
    float S = 0.f, SS = 0.f;
    #pragma unroll
    for (int i = 0; i < 8; i++) { S += sh_s[i]; SS += sh_ss[i]; }
    float mu  = S * (1.0f / D_);
    float var = SS * (1.0f / D_) - mu * mu;
    float inv = rsqrtf(var + 1e-5f);
    float4 g4 = ((const float4*)g)[tid];
    float4 b4 = ((const float4*)bta)[tid];
    __half2 o0 = __floats2half2_rn((v.x - mu) * inv * g4.x + b4.x,
                                   (v.y - mu) * inv * g4.y + b4.y);
    __half2 o1 = __floats2half2_rn((v.z - mu) * inv * g4.z + b4.z,
                                   (v.w - mu) * inv * g4.w + b4.w);
    __half2* yp = (__half2*)(y + (size_t)row * D_) + tid * 2;
    yp[0] = o0; yp[1] = o1;
}

// ---------------- fp16 tensor-core GEMM 128x128, K-stage 32, 2-stage --------
// C[M,N] = A[M,K] (half, row-major) * Bt[N,K] (half) + epilogue (fp32 accum)
// EPI bit0: +bias  bit1: gelu  bit2: +res(fp32)
// OUTH: 1 -> C is __half*, 0 -> C is float*
template <int EPI, int OUTH>
__global__ __launch_bounds__(256, 2) void hgemm_kernel(
    const __half* __restrict__ A, const __half* __restrict__ Bt,
    void* __restrict__ Cv, const float* __restrict__ bias,
    const float* __restrict__ res, int M, int N, int K)
{
    __shared__ uint32_t As[2][128][20];   // [m][k2], cols 0..15 used
    __shared__ uint32_t Bs[2][128][20];   // [n][k2]
    int tid = threadIdx.x;
    int lane = tid & 31, warp = tid >> 5;
    int g = lane >> 2, tg = lane & 3;
    int mw = (warp & 3) << 5;
    int nw = (warp >> 2) << 6;
    int bm = blockIdx.y, bn = blockIdx.x;
    const __half* Ab = A  + (size_t)bm * 128 * K;
    const __half* Bb = Bt + (size_t)bn * 128 * K;

    float acc[2][8][4];
    #pragma unroll
    for (int mi = 0; mi < 2; mi++)
        #pragma unroll
        for (int j = 0; j < 8; j++)
            #pragma unroll
            for (int q = 0; q < 4; q++) acc[mi][j][q] = 0.f;

    int lrow = tid >> 1;            // 0..127
    int lseg = (tid & 1) << 3;      // uint32 offset 0 or 8 (16 halves)

    cp_async16(&As[0][lrow][lseg],     Ab + (size_t)lrow * K + (lseg << 1));
    cp_async16(&As[0][lrow][lseg + 4], Ab + (size_t)lrow * K + (lseg << 1) + 8);
    cp_async16(&Bs[0][lrow][lseg],     Bb + (size_t)lrow * K + (lseg << 1));
    cp_async16(&Bs[0][lrow][lseg + 4], Bb + (size_t)lrow * K + (lseg << 1) + 8);
    CP_COMMIT();

    int nk = K >> 5;
    for (int it = 0; it < nk; it++) {
        int buf = it & 1;
        CP_WAIT0();
        __syncthreads();
        if (it + 1 < nk) {
            int kt = (it + 1) << 5;
            int nb2 = buf ^ 1;
            cp_async16(&As[nb2][lrow][lseg],     Ab + (size_t)lrow * K + kt + (lseg << 1));
            cp_async16(&As[nb2][lrow][lseg + 4], Ab + (size_t)lrow * K + kt + (lseg << 1) + 8);
            cp_async16(&Bs[nb2][lrow][lseg],     Bb + (size_t)lrow * K + kt + (lseg << 1));
            cp_async16(&Bs[nb2][lrow][lseg + 4], Bb + (size_t)lrow * K + kt + (lseg << 1) + 8);
            CP_COMMIT();
        }
        #pragma unroll
        for (int ks = 0; ks < 2; ks++) {      // two k16 steps
            int k2b = ks << 3;
            uint32_t af[2][4], bf[8][2];
            #pragma unroll
            for (int mi = 0; mi < 2; mi++) {
                int r = mw + (mi << 4) + g;
                af[mi][0] = As[buf][r    ][k2b + tg];
                af[mi][1] = As[buf][r + 8][k2b + tg];
                af[mi][2] = As[buf][r    ][k2b + 4 + tg];
                af[mi][3] = As[buf][r + 8][k2b + 4 + tg];
            }
            #pragma unroll
            for (int j = 0; j < 8; j++) {
                int n = nw + (j << 3) + g;
                bf[j][0] = Bs[buf][n][k2b + tg];
                bf[j][1] = Bs[buf][n][k2b + 4 + tg];
            }
            #pragma unroll
            for (int mi = 0; mi < 2; mi++)
                #pragma unroll
                for (int j = 0; j < 8; j++)
                    mma_f16(acc[mi][j], af[mi], bf[j]);
        }
    }

    #pragma unroll
    for (int mi = 0; mi < 2; mi++) {
        int r0 = bm * 128 + mw + (mi << 4) + g;
        int r1 = r0 + 8;
        #pragma unroll
        for (int j = 0; j < 8; j++) {
            int c = bn * 128 + nw + (j << 3) + (tg << 1);
            float v0 = acc[mi][j][0], v1 = acc[mi][j][1];
            float v2 = acc[mi][j][2], v3 = acc[mi][j][3];
            if (EPI & 1) {
                float2 bv = *(const float2*)(bias + c);
                v0 += bv.x; v1 += bv.y; v2 += bv.x; v3 += bv.y;
            }
            if (EPI & 2) {
                v0 = geluf(v0); v1 = geluf(v1);
                v2 = geluf(v2); v3 = geluf(v3);
            }
            if (EPI & 4) {
                float2 ra = *(const float2*)(res + (size_t)r0 * N + c);
                float2 rb = *(const float2*)(res + (size_t)r1 * N + c);
                v0 += ra.x; v1 += ra.y; v2 += rb.x; v3 += rb.y;
            }
            if (OUTH) {
                __half* Ch = (__half*)Cv;
                *(__half2*)(Ch + (size_t)r0 * N + c) = __floats2half2_rn(v0, v1);
                *(__half2*)(Ch + (size_t)r1 * N + c) = __floats2half2_rn(v2, v3);
            } else {
                float* Cf = (float*)Cv;
                float2 w0 = { v0, v1 }, w1 = { v2, v3 };
                *(float2*)(Cf + (size_t)r0 * N + c) = w0;
                *(float2*)(Cf + (size_t)r1 * N + c) = w1;
            }
        }
    }
}

// ---------------- flash attention, fp16 mma ---------------------------------
// Block: (bh, 64 q-rows). 8 warps 4(m)x2(n), warp tile 16x32.
// Q/K/P row-major half pitch 36 uint32 (64 halves + pad); V row-major, PV
// B-fragments via ldmatrix.x2.trans. Softmax fp32.
#define FQP 36
#define FLASH_SMEM_U32 (6*64*FQP + 256)
#define FLASH_SMEM_BYTES (FLASH_SMEM_U32 * 4)

__global__ __launch_bounds__(256, 2) void flash_attn_kernel()
{
    extern __shared__ uint32_t usm[];
    uint32_t* Qs = usm;                    // [64][FQP]
    uint32_t* Ks = Qs + 64 * FQP;          // [2][64][FQP]
    uint32_t* Vs = Ks + 2 * 64 * FQP;      // [2][64][FQP]
    uint32_t* Ps = Vs + 2 * 64 * FQP;      // [64][FQP]
    float* redm  = (float*)(Ps + 64 * FQP); // [128]
    float* reds  = redm + 128;              // [128]

    int bh = blockIdx.y;
    int b = bh >> 4, h = bh & 15;
    int t0 = blockIdx.x * 64;
    int tid = threadIdx.x;
    int lane = tid & 31, warp = tid >> 5;
    int g = lane >> 2, tg = lane & 3;
    int wm = warp & 3, wn = warp >> 2;
    int m0r = (wm << 4) + g;
    int nb  = wn << 5;

    const __half* qbase = g_qkv + ((size_t)b * T_) * TD3_ + h * 64;
    int lrow = tid >> 3;              // 0..31 (+32)
    int lch  = tid & 7;               // 16B chunk 0..7

    // prefetch Q tile
    #pragma unroll
    for (int i = 0; i < 2; i++) {
        int row = lrow + i * 32;
        cp_async16(&Qs[row * FQP + lch * 4], qbase + (size_t)(t0 + row) * TD3_ + lch * 8);
    }
    CP_COMMIT();
    // prefetch K/V tile 0
    #pragma unroll
    for (int i = 0; i < 2; i++) {
        int row = lrow + i * 32;
        cp_async16(&Ks[row * FQP + lch * 4], qbase + 1024 + (size_t)row * TD3_ + lch * 8);
        cp_async16(&Vs[row * FQP + lch * 4], qbase + 2048 + (size_t)row * TD3_ + lch * 8);
    }
    CP_COMMIT();

    float accO[4][4];
    #pragma unroll
    for (int j = 0; j < 4; j++)
        #pragma unroll
        for (int q = 0; q < 4; q++) accO[j][q] = 0.f;
    float m0 = -3.0e38f, m1 = -3.0e38f, l0 = 0.f, l1 = 0.f;

    for (int st = 0; st < 16; st++) {
        int buf = st & 1;
        uint32_t* Kb = Ks + buf * 64 * FQP;
        uint32_t* Vb = Vs + buf * 64 * FQP;
        uint32_t vb_addr = (uint32_t)__cvta_generic_to_shared(Vb);
        CP_WAIT0();
        __syncthreads();
        if (st + 1 < 16) {
            int s1 = (st + 1) * 64;
            uint32_t* Kn = Ks + (buf ^ 1) * 64 * FQP;
            uint32_t* Vn = Vs + (buf ^ 1) * 64 * FQP;
            #pragma unroll
            for (int i = 0; i < 2; i++) {
                int row = lrow + i * 32;
                cp_async16(&Kn[row * FQP + lch * 4], qbase + 1024 + (size_t)(s1 + row) * TD3_ + lch * 8);
                cp_async16(&Vn[row * FQP + lch * 4], qbase + 2048 + (size_t)(s1 + row) * TD3_ + lch * 8);
            }
            CP_COMMIT();
        }

        // S = Q K^T  (4 k16 steps over e=64)
        float sacc[4][4];
        #pragma unroll
        for (int j = 0; j < 4; j++)
            #pragma unroll
            for (int q = 0; q < 4; q++) sacc[j][q] = 0.f;
        #pragma unroll
        for (int ks = 0; ks < 4; ks++) {
            int kb = ks << 3;
            uint32_t af[4], bf[4][2];
            af[0] = Qs[m0r * FQP + kb + tg];
            af[1] = Qs[(m0r + 8) * FQP + kb + tg];
            af[2] = Qs[m0r * FQP + kb + 4 + tg];
            af[3] = Qs[(m0r + 8) * FQP + kb + 4 + tg];
            #pragma unroll
            for (int j = 0; j < 4; j++) {
                int n = nb + (j << 3) + g;
                bf[j][0] = Kb[n * FQP + kb + tg];
                bf[j][1] = Kb[n * FQP + kb + 4 + tg];
            }
            #pragma unroll
            for (int j = 0; j < 4; j++) mma_f16(sacc[j], af, bf[j]);
        }

        // scale + row max
        float rmax0 = -3.0e38f, rmax1 = -3.0e38f;
        #pragma unroll
        for (int j = 0; j < 4; j++) {
            #pragma unroll
            for (int q = 0; q < 4; q++) sacc[j][q] *= 0.125f;
            rmax0 = fmaxf(rmax0, fmaxf(sacc[j][0], sacc[j][1]));
            rmax1 = fmaxf(rmax1, fmaxf(sacc[j][2], sacc[j][3]));
        }
        rmax0 = fmaxf(rmax0, __shfl_xor_sync(0xffffffffu, rmax0, 1));
        rmax0 = fmaxf(rmax0, __shfl_xor_sync(0xffffffffu, rmax0, 2));
        rmax1 = fmaxf(rmax1, __shfl_xor_sync(0xffffffffu, rmax1, 1));
        rmax1 = fmaxf(rmax1, __shfl_xor_sync(0xffffffffu, rmax1, 2));
        if (tg == 0) {
            redm[m0r * 2 + wn]       = rmax0;
            redm[(m0r + 8) * 2 + wn] = rmax1;
        }
        __syncthreads();
        float mn0 = fmaxf(m0, fmaxf(redm[m0r * 2], redm[m0r * 2 + 1]));
        float mn1 = fmaxf(m1, fmaxf(redm[(m0r + 8) * 2], redm[(m0r + 8) * 2 + 1]));
        float alpha0 = __expf(m0 - mn0);
        float alpha1 = __expf(m1 - mn1);
        m0 = mn0; m1 = mn1;

        // P = exp(S - m), store half pairs, partial row sums
        float rs0 = 0.f, rs1 = 0.f;
        #pragma unroll
        for (int j = 0; j < 4; j++) {
            float p00 = __expf(sacc[j][0] - mn0);
            float p01 = __expf(sacc[j][1] - mn0);
            float p10 = __expf(sacc[j][2] - mn1);
            float p11 = __expf(sacc[j][3] - mn1);
            rs0 += p00 + p01; rs1 += p10 + p11;
            int cu = (nb >> 1) + (j << 2) + tg;     // uint32 col (half pair)
            Ps[m0r * FQP + cu]       = h2u(__floats2half2_rn(p00, p01));
            Ps[(m0r + 8) * FQP + cu] = h2u(__floats2half2_rn(p10, p11));
        }
        rs0 += __shfl_xor_sync(0xffffffffu, rs0, 1);
        rs0 += __shfl_xor_sync(0xffffffffu, rs0, 2);
        rs1 += __shfl_xor_sync(0xffffffffu, rs1, 1);
        rs1 += __shfl_xor_sync(0xffffffffu, rs1, 2);
        if (tg == 0) {
            reds[m0r * 2 + wn]       = rs0;
            reds[(m0r + 8) * 2 + wn] = rs1;
        }
        #pragma unroll
        for (int j = 0; j < 4; j++) {
            accO[j][0] *= alpha0; accO[j][1] *= alpha0;
            accO[j][2] *= alpha1; accO[j][3] *= alpha1;
        }
        __syncthreads();
        l0 = l0 * alpha0 + reds[m0r * 2] + reds[m0r * 2 + 1];
        l1 = l1 * alpha1 + reds[(m0r + 8) * 2] + reds[(m0r + 8) * 2 + 1];

        // O += P @ V  (A from Ps; B via ldmatrix.trans on row-major V)
        #pragma unroll
        for (int ks = 0; ks < 4; ks++) {
            int kb = ks << 3;
            uint32_t af[4], bf[4][2];
            af[0] = Ps[m0r * FQP + kb + tg];
            af[1] = Ps[(m0r + 8) * FQP + kb + tg];
            af[2] = Ps[m0r * FQP + kb + 4 + tg];
            af[3] = Ps[(m0r + 8) * FQP + kb + 4 + tg];
            uint32_t rowa = vb_addr + (uint32_t)((ks * 16 + (lane & 15)) * (FQP * 4));
            #pragma unroll
            for (int j = 0; j < 4; j++) {
                int cb = nb + (j << 3);
                ldmatrix_x2_trans(bf[j][0], bf[j][1], rowa + cb * 2);
            }
            #pragma unroll
            for (int j = 0; j < 4; j++) mma_f16(accO[j], af, bf[j]);
        }
    }

    float inv0 = 1.0f / l0;
    float inv1 = 1.0f / l1;
    __half* out0 = g_ctx + ((size_t)b * T_ + t0 + m0r) * D_ + h * 64;
    __half* out1 = out0 + (size_t)8 * D_;
    #pragma unroll
    for (int j = 0; j < 4; j++) {
        int col = nb + (j << 3) + (tg << 1);
        *(__half2*)(out0 + col) = __floats2half2_rn(accO[j][0] * inv0, accO[j][1] * inv0);
        *(__half2*)(out1 + col) = __floats2half2_rn(accO[j][2] * inv1, accO[j][3] * inv1);
    }
}

// ---------------- launcher --------------------------------------------------
extern "C" void kernel_launch(void* const* d_in, const int* in_sizes, int n_in,
                              void* d_out, int out_size)
{
    const float* x    = (const float*)d_in[0];
    const float* ln1g = (const float*)d_in[1];
    const float* ln1b = (const float*)d_in[2];
    const float* ln2g = (const float*)d_in[3];
    const float* ln2b = (const float*)d_in[4];
    const float* Wq   = (const float*)d_in[5];
    const float* bq   = (const float*)d_in[6];
    const float* Wk   = (const float*)d_in[7];
    const float* bk   = (const float*)d_in[8];
    const float* Wv   = (const float*)d_in[9];
    const float* bv   = (const float*)d_in[10];
    const float* Wo   = (const float*)d_in[11];
    const float* bo   = (const float*)d_in[12];
    const float* W1   = (const float*)d_in[13];
    const float* b1   = (const float*)d_in[14];
    const float* W2   = (const float*)d_in[15];
    const float* b2   = (const float*)d_in[16];
    float* out = (float*)d_out;

    static __half* h_     = nullptr;
    static __half* qkv_   = nullptr;
    static float*  wcat_  = nullptr;
    static __half* wcatT_ = nullptr;
    static float*  bcat_  = nullptr;
    static __half* ctx_   = nullptr;
    static __half* ffa_   = nullptr;
    static __half* wrnd_  = nullptr;
    if (!h_) {   // pointer cache only — identical work every call
        cudaGetSymbolAddress((void**)&h_,     g_h);
        cudaGetSymbolAddress((void**)&qkv_,   g_qkv);
        cudaGetSymbolAddress((void**)&wcat_,  g_wcat);
        cudaGetSymbolAddress((void**)&wcatT_, g_wcatT);
        cudaGetSymbolAddress((void**)&bcat_,  g_bcat);
        cudaGetSymbolAddress((void**)&ctx_,   g_ctx);
        cudaGetSymbolAddress((void**)&ffa_,   g_ffa);
        cudaGetSymbolAddress((void**)&wrnd_,  g_wrndh);
        cudaFuncSetAttribute(flash_attn_kernel,
                             cudaFuncAttributeMaxDynamicSharedMemorySize, FLASH_SMEM_BYTES);
    }
    __half* woT = wrnd_;
    __half* w1T = wrnd_ + (size_t)D_ * D_;
    __half* w2T = wrnd_ + (size_t)D_ * D_ + (size_t)D_ * FF_;

    // 1) weight prep: repack, then transpose+halve everything to [N][K]
    repack_kernel<<<(D_ * TD3_ + 255) / 256, 256>>>(Wq, Wk, Wv, bq, bk, bv);
    transTh_kernel<<<dim3(TD3_ / 32, D_ / 32), 256>>>(wcat_, wcatT_, D_, TD3_);
    transTh_kernel<<<dim3(D_ / 32, D_ / 32), 256>>>(Wo, woT, D_, D_);
    transTh_kernel<<<dim3(FF_ / 32, D_ / 32), 256>>>(W1, w1T, D_, FF_);
    transTh_kernel<<<dim3(D_ / 32, FF_ / 32), 256>>>(W2, w2T, FF_, D_);
    // 2) ln1 -> h (half)
    ln_kernel<<<BT_, 256>>>(x, ln1g, ln1b, h_);
    // 3) QKV = h @ Wcat + bcat -> half
    hgemm_kernel<1, 1><<<dim3(TD3_ / 128, BT_ / 128), 256>>>(
        h_, wcatT_, qkv_, bcat_, nullptr, BT_, TD3_, D_);
    // 4-6) fused attention -> ctx (half)
    flash_attn_kernel<<<dim3(16, B_ * H_), 256, FLASH_SMEM_BYTES>>>();
    // 7) X1 = x + ctx @ Wo + bo -> out (fp32)
    hgemm_kernel<5, 0><<<dim3(D_ / 128, BT_ / 128), 256>>>(
        ctx_, woT, out, bo, x, BT_, D_, D_);
    // 8) ln2 -> h (half)
    ln_kernel<<<BT_, 256>>>(out, ln2g, ln2b, h_);
    // 9) ffa = gelu(h @ W1 + b1) -> half
    hgemm_kernel<3, 1><<<dim3(FF_ / 128, BT_ / 128), 256>>>(
        h_, w1T, ffa_, b1, nullptr, BT_, FF_, D_);
    // 10) out = X1 + ffa @ W2 + b2 -> fp32
    hgemm_kernel<5, 0><<<dim3(D_ / 128, BT_ / 128), 256>>>(
        ffa_, w2T, out, b2, out, BT_, D_, FF_);
}

// round 15
// speedup vs baseline: 1.7988x; 1.1020x over previous
#include <cuda_runtime.h>
#include <cuda_fp16.h>
#include <cstdint>
#include <cstddef>
#include <cstring>

#define B_  8
#define T_  1024
#define D_  1024
#define H_  16
#define HD_ 64
#define FF_ 4096
#define BT_ (B_*T_)            // 8192
#define TD3_ (3*D_)            // 3072

// ---------------- scratch (device globals: allocation-guard-safe) ----------
__device__ __half g_h[(size_t)BT_ * D_];         // 16 MB (ln output, half)
__device__ __half g_qkv[(size_t)BT_ * TD3_];     // 48 MB (QKV, half)
__device__ float  g_wcat[(size_t)D_ * TD3_];     // 12 MB (staging fp32)
__device__ __half g_wcatT[(size_t)TD3_ * D_];    // 6 MB  [N][K] half
__device__ float  g_bcat[TD3_];
__device__ __half g_ctx[(size_t)BT_ * D_];       // 16 MB (flash out, half)
__device__ __half g_ffa[(size_t)BT_ * FF_];      // 64 MB (gelu out, half)
__device__ __half g_wrndh[(size_t)D_*D_ + (size_t)D_*FF_ + (size_t)FF_*D_]; // 18 MB

// ---------------- helpers ---------------------------------------------------
__device__ __forceinline__ float geluf(float x) {
    return 0.5f * x * (1.0f + erff(x * 0.70710678118654752f));
}
__device__ __forceinline__ uint32_t h2u(__half2 v) {
    uint32_t r; memcpy(&r, &v, 4); return r;
}
__device__ __forceinline__ void mma_f16(float c[4], const uint32_t a[4], const uint32_t b[2]) {
    asm volatile(
        "mma.sync.aligned.m16n8k16.row.col.f32.f16.f16.f32 "
        "{%0,%1,%2,%3}, {%4,%5,%6,%7}, {%8,%9}, {%0,%1,%2,%3};"
        : "+f"(c[0]), "+f"(c[1]), "+f"(c[2]), "+f"(c[3])
        : "r"(a[0]), "r"(a[1]), "r"(a[2]), "r"(a[3]), "r"(b[0]), "r"(b[1]));
}
__device__ __forceinline__ void ldmx4(uint32_t& r0, uint32_t& r1, uint32_t& r2, uint32_t& r3,
                                      uint32_t saddr) {
    asm volatile("ldmatrix.sync.aligned.m8n8.x4.shared.b16 {%0,%1,%2,%3}, [%4];"
                 : "=r"(r0), "=r"(r1), "=r"(r2), "=r"(r3) : "r"(saddr));
}
__device__ __forceinline__ void ldmatrix_x2_trans(uint32_t& r0, uint32_t& r1, uint32_t saddr) {
    asm volatile("ldmatrix.sync.aligned.m8n8.x2.trans.shared.b16 {%0, %1}, [%2];"
                 : "=r"(r0), "=r"(r1) : "r"(saddr));
}
__device__ __forceinline__ void cp_async16(void* sptr, const void* gptr) {
    uint32_t s = (uint32_t)__cvta_generic_to_shared(sptr);
    asm volatile("cp.async.cg.shared.global [%0], [%1], 16;" :: "r"(s), "l"(gptr));
}
#define CP_COMMIT() asm volatile("cp.async.commit_group;")
#define CP_WAIT0()  asm volatile("cp.async.wait_group 0;")

// ---------------- weight repack: Wq/Wk/Wv [H,D,HD] -> Wcat fp32 [D, 3D] -----
__global__ __launch_bounds__(256) void repack_kernel(
    const float* __restrict__ Wq, const float* __restrict__ Wk, const float* __restrict__ Wv,
    const float* __restrict__ bq, const float* __restrict__ bk, const float* __restrict__ bv)
{
    int t = blockIdx.x * blockDim.x + threadIdx.x;
    if (t >= D_ * TD3_) return;
    int d = t / TD3_;
    int n = t - d * TD3_;
    int part = n >> 10;
    int m = n & (D_ - 1);
    int h = m >> 6, e = m & 63;
    const float* W = (part == 0) ? Wq : (part == 1) ? Wk : Wv;
    g_wcat[t] = W[((size_t)h * D_ + d) * HD_ + e];
    if (d == 0) {
        const float* bb = (part == 0) ? bq : (part == 1) ? bk : bv;
        g_bcat[n] = bb[m];
    }
}

// ---------------- tiled transpose fp32[R][C] -> half[C][R] ------------------
__global__ __launch_bounds__(256) void transTh_kernel(
    const float* __restrict__ src, __half* __restrict__ dst, int R, int C)
{
    __shared__ float tile[32][33];
    int bx = blockIdx.x * 32, by = blockIdx.y * 32;
    int tx = threadIdx.x & 31, ty = threadIdx.x >> 5;   // 32 x 8
    #pragma unroll
    for (int i = 0; i < 32; i += 8)
        tile[ty + i][tx] = src[(size_t)(by + ty + i) * C + bx + tx];
    __syncthreads();
    #pragma unroll
    for (int i = 0; i < 32; i += 8)
        dst[(size_t)(bx + ty + i) * R + by + tx] = __float2half(tile[tx][ty + i]);
}

// ---------------- layernorm: fp32 in -> half out ----------------------------
__global__ __launch_bounds__(256) void ln_kernel(
    const float* __restrict__ x, const float* __restrict__ g,
    const float* __restrict__ bta, __half* __restrict__ y)
{
    int row = blockIdx.x;
    int tid = threadIdx.x;
    const float4* xr = (const float4*)(x + (size_t)row * D_);
    float4 v = xr[tid];
    float s  = v.x + v.y + v.z + v.w;
    float ss = v.x*v.x + v.y*v.y + v.z*v.z + v.w*v.w;
    __shared__ float sh_s[8], sh_ss[8];
    #pragma unroll
    for (int o = 16; o > 0; o >>= 1) {
        s  += __shfl_down_sync(0xffffffffu, s,  o);
        ss += __shfl_down_sync(0xffffffffu, ss, o);
    }
    if ((tid & 31) == 0) { sh_s[tid >> 5] = s; sh_ss[tid >> 5] = ss; }
    __syncthreads();
    float S = 0.f, SS = 0.f;
    #pragma unroll
    for (int i = 0; i < 8; i++) { S += sh_s[i]; SS += sh_ss[i]; }
    float mu  = S * (1.0f / D_);
    float var = SS * (1.0f / D_) - mu * mu;
    float inv = rsqrtf(var + 1e-5f);
    float4 g4 = ((const float4*)g)[tid];
    float4 b4 = ((const float4*)bta)[tid];
    __half2 o0 = __floats2half2_rn((v.x - mu) * inv * g4.x + b4.x,
                                   (v.y - mu) * inv * g4.y + b4.y);
    __half2 o1 = __floats2half2_rn((v.z - mu) * inv * g4.z + b4.z,
                                   (v.w - mu) * inv * g4.w + b4.w);
    __half2* yp = (__half2*)(y + (size_t)row * D_) + tid * 2;
    yp[0] = o0; yp[1] = o1;
}

// ---------------- fp16 tensor-core GEMM 128x128, K-stage 32, 2-stage --------
// C[M,N] = A[M,K] (half, row-major) * Bt[N,K] (half) + epilogue (fp32 accum)
// Fragments loaded via ldmatrix.x4 (6 loads per k16 step, was 24 LDS).
// EPI bit0: +bias  bit1: gelu  bit2: +res(fp32)
// OUTH: 1 -> C is __half*, 0 -> C is float*
template <int EPI, int OUTH>
__global__ __launch_bounds__(256, 2) void hgemm_kernel(
    const __half* __restrict__ A, const __half* __restrict__ Bt,
    void* __restrict__ Cv, const float* __restrict__ bias,
    const float* __restrict__ res, int M, int N, int K)
{
    __shared__ uint32_t As[2][128][20];   // [m][k2], cols 0..15 used
    __shared__ uint32_t Bs[2][128][20];   // [n][k2]
    int tid = threadIdx.x;
    int lane = tid & 31, warp = tid >> 5;
    int g = lane >> 2, tg = lane & 3;
    int mw = (warp & 3) << 5;
    int nw = (warp >> 2) << 6;
    int bm = blockIdx.y, bn = blockIdx.x;
    const __half* Ab = A  + (size_t)bm * 128 * K;
    const __half* Bb = Bt + (size_t)bn * 128 * K;

    float acc[2][8][4];
    #pragma unroll
    for (int mi = 0; mi < 2; mi++)
        #pragma unroll
        for (int j = 0; j < 8; j++)
            #pragma unroll
            for (int q = 0; q < 4; q++) acc[mi][j][q] = 0.f;

    int lrow = tid >> 1;            // 0..127
    int lseg = (tid & 1) << 3;      // uint32 offset 0 or 8 (16 halves)

    // ldmatrix per-thread byte offsets within a tile (independent of buf/ks):
    // A (per mi): mat q=lane>>3: rows base+(q&1)*8+(lane&7), col (q>>1)*4 u32
    uint32_t as0 = (uint32_t)__cvta_generic_to_shared(&As[0][0][0]);
    uint32_t bs0 = (uint32_t)__cvta_generic_to_shared(&Bs[0][0][0]);
    uint32_t aoff[2];
    #pragma unroll
    for (int mi = 0; mi < 2; mi++) {
        int row = mw + (mi << 4) + ((lane >> 3) & 1) * 8 + (lane & 7);
        int col = (lane >> 4) << 2;
        aoff[mi] = (uint32_t)((row * 20 + col) * 4);
    }
    // B (per jj): mat q: rows nw+16jj+(q>>1)*8+(lane&7), col (q&1)*4 u32
    uint32_t boff[4];
    #pragma unroll
    for (int jj = 0; jj < 4; jj++) {
        int row = nw + (jj << 4) + ((lane >> 4) << 3) + (lane & 7);
        int col = ((lane >> 3) & 1) << 2;
        boff[jj] = (uint32_t)((row * 20 + col) * 4);
    }
    const uint32_t TILE_BYTES = 128 * 20 * 4;

    cp_async16(&As[0][lrow][lseg],     Ab + (size_t)lrow * K + (lseg << 1));
    cp_async16(&As[0][lrow][lseg + 4], Ab + (size_t)lrow * K + (lseg << 1) + 8);
    cp_async16(&Bs[0][lrow][lseg],     Bb + (size_t)lrow * K + (lseg << 1));
    cp_async16(&Bs[0][lrow][lseg + 4], Bb + (size_t)lrow * K + (lseg << 1) + 8);
    CP_COMMIT();

    int nk = K >> 5;
    for (int it = 0; it < nk; it++) {
        int buf = it & 1;
        CP_WAIT0();
        __syncthreads();
        if (it + 1 < nk) {
            int kt = (it + 1) << 5;
            int nb2 = buf ^ 1;
            cp_async16(&As[nb2][lrow][lseg],     Ab + (size_t)lrow * K + kt + (lseg << 1));
            cp_async16(&As[nb2][lrow][lseg + 4], Ab + (size_t)lrow * K + kt + (lseg << 1) + 8);
            cp_async16(&Bs[nb2][lrow][lseg],     Bb + (size_t)lrow * K + kt + (lseg << 1));
            cp_async16(&Bs[nb2][lrow][lseg + 4], Bb + (size_t)lrow * K + kt + (lseg << 1) + 8);
            CP_COMMIT();
        }
        uint32_t ab = as0 + buf * TILE_BYTES;
        uint32_t bb2 = bs0 + buf * TILE_BYTES;
        #pragma unroll
        for (int ks = 0; ks < 2; ks++) {      // two k16 steps
            uint32_t kbyte = (uint32_t)(ks * 32);   // 8 u32 = 32 B
            uint32_t af[2][4], bf[8][2];
            #pragma unroll
            for (int mi = 0; mi < 2; mi++)
                ldmx4(af[mi][0], af[mi][1], af[mi][2], af[mi][3],
                      ab + aoff[mi] + kbyte);
            #pragma unroll
            for (int jj = 0; jj < 4; jj++)
                ldmx4(bf[2*jj][0], bf[2*jj][1], bf[2*jj+1][0], bf[2*jj+1][1],
                      bb2 + boff[jj] + kbyte);
            #pragma unroll
            for (int mi = 0; mi < 2; mi++)
                #pragma unroll
                for (int j = 0; j < 8; j++)
                    mma_f16(acc[mi][j], af[mi], bf[j]);
        }
    }

    #pragma unroll
    for (int mi = 0; mi < 2; mi++) {
        int r0 = bm * 128 + mw + (mi << 4) + g;
        int r1 = r0 + 8;
        #pragma unroll
        for (int j = 0; j < 8; j++) {
            int c = bn * 128 + nw + (j << 3) + (tg << 1);
            float v0 = acc[mi][j][0], v1 = acc[mi][j][1];
            float v2 = acc[mi][j][2], v3 = acc[mi][j][3];
            if (EPI & 1) {
                float2 bv = *(const float2*)(bias + c);
                v0 += bv.x; v1 += bv.y; v2 += bv.x; v3 += bv.y;
            }
            if (EPI & 2) {
                v0 = geluf(v0); v1 = geluf(v1);
                v2 = geluf(v2); v3 = geluf(v3);
            }
            if (EPI & 4) {
                float2 ra = *(const float2*)(res + (size_t)r0 * N + c);
                float2 rb = *(const float2*)(res + (size_t)r1 * N + c);
                v0 += ra.x; v1 += ra.y; v2 += rb.x; v3 += rb.y;
            }
            if (OUTH) {
                __half* Ch = (__half*)Cv;
                *(__half2*)(Ch + (size_t)r0 * N + c) = __floats2half2_rn(v0, v1);
                *(__half2*)(Ch + (size_t)r1 * N + c) = __floats2half2_rn(v2, v3);
            } else {
                float* Cf = (float*)Cv;
                float2 w0 = { v0, v1 }, w1 = { v2, v3 };
                *(float2*)(Cf + (size_t)r0 * N + c) = w0;
                *(float2*)(Cf + (size_t)r1 * N + c) = w1;
            }
        }
    }
}

// ---------------- flash attention, fp16 mma (unchanged from R14) ------------
#define FQP 36
#define FLASH_SMEM_U32 (6*64*FQP + 256)
#define FLASH_SMEM_BYTES (FLASH_SMEM_U32 * 4)

__global__ __launch_bounds__(256, 2) void flash_attn_kernel()
{
    extern __shared__ uint32_t usm[];
    uint32_t* Qs = usm;                    // [64][FQP]
    uint32_t* Ks = Qs + 64 * FQP;          // [2][64][FQP]
    uint32_t* Vs = Ks + 2 * 64 * FQP;      // [2][64][FQP]
    uint32_t* Ps = Vs + 2 * 64 * FQP;      // [64][FQP]
    float* redm  = (float*)(Ps + 64 * FQP); // [128]
    float* reds  = redm + 128;              // [128]

    int bh = blockIdx.y;
    int b = bh >> 4, h = bh & 15;
    int t0 = blockIdx.x * 64;
    int tid = threadIdx.x;
    int lane = tid & 31, warp = tid >> 5;
    int g = lane >> 2, tg = lane & 3;
    int wm = warp & 3, wn = warp >> 2;
    int m0r = (wm << 4) + g;
    int nb  = wn << 5;

    const __half* qbase = g_qkv + ((size_t)b * T_) * TD3_ + h * 64;
    int lrow = tid >> 3;              // 0..31 (+32)
    int lch  = tid & 7;               // 16B chunk 0..7

    #pragma unroll
    for (int i = 0; i < 2; i++) {
        int row = lrow + i * 32;
        cp_async16(&Qs[row * FQP + lch * 4], qbase + (size_t)(t0 + row) * TD3_ + lch * 8);
    }
    CP_COMMIT();
    #pragma unroll
    for (int i = 0; i < 2; i++) {
        int row = lrow + i * 32;
        cp_async16(&Ks[row * FQP + lch * 4], qbase + 1024 + (size_t)row * TD3_ + lch * 8);
        cp_async16(&Vs[row * FQP + lch * 4], qbase + 2048 + (size_t)row * TD3_ + lch * 8);
    }
    CP_COMMIT();

    float accO[4][4];
    #pragma unroll
    for (int j = 0; j < 4; j++)
        #pragma unroll
        for (int q = 0; q < 4; q++) accO[j][q] = 0.f;
    float m0 = -3.0e38f, m1 = -3.0e38f, l0 = 0.f, l1 = 0.f;

    for (int st = 0; st < 16; st++) {
        int buf = st & 1;
        uint32_t* Kb = Ks + buf * 64 * FQP;
        uint32_t* Vb = Vs + buf * 64 * FQP;
        uint32_t vb_addr = (uint32_t)__cvta_generic_to_shared(Vb);
        CP_WAIT0();
        __syncthreads();
        if (st + 1 < 16) {
            int s1 = (st + 1) * 64;
            uint32_t* Kn = Ks + (buf ^ 1) * 64 * FQP;
            uint32_t* Vn = Vs + (buf ^ 1) * 64 * FQP;
            #pragma unroll
            for (int i = 0; i < 2; i++) {
                int row = lrow + i * 32;
                cp_async16(&Kn[row * FQP + lch * 4], qbase + 1024 + (size_t)(s1 + row) * TD3_ + lch * 8);
                cp_async16(&Vn[row * FQP + lch * 4], qbase + 2048 + (size_t)(s1 + row) * TD3_ + lch * 8);
            }
            CP_COMMIT();
        }

        float sacc[4][4];
        #pragma unroll
        for (int j = 0; j < 4; j++)
            #pragma unroll
            for (int q = 0; q < 4; q++) sacc[j][q] = 0.f;
        #pragma unroll
        for (int ks = 0; ks < 4; ks++) {
            int kb = ks << 3;
            uint32_t af[4], bf[4][2];
            af[0] = Qs[m0r * FQP + kb + tg];
            af[1] = Qs[(m0r + 8) * FQP + kb + tg];
            af[2] = Qs[m0r * FQP + kb + 4 + tg];
            af[3] = Qs[(m0r + 8) * FQP + kb + 4 + tg];
            #pragma unroll
            for (int j = 0; j < 4; j++) {
                int n = nb + (j << 3) + g;
                bf[j][0] = Kb[n * FQP + kb + tg];
                bf[j][1] = Kb[n * FQP + kb + 4 + tg];
            }
            #pragma unroll
            for (int j = 0; j < 4; j++) mma_f16(sacc[j], af, bf[j]);
        }

        float rmax0 = -3.0e38f, rmax1 = -3.0e38f;
        #pragma unroll
        for (int j = 0; j < 4; j++) {
            #pragma unroll
            for (int q = 0; q < 4; q++) sacc[j][q] *= 0.125f;
            rmax0 = fmaxf(rmax0, fmaxf(sacc[j][0], sacc[j][1]));
            rmax1 = fmaxf(rmax1, fmaxf(sacc[j][2], sacc[j][3]));
        }
        rmax0 = fmaxf(rmax0, __shfl_xor_sync(0xffffffffu, rmax0, 1));
        rmax0 = fmaxf(rmax0, __shfl_xor_sync(0xffffffffu, rmax0, 2));
        rmax1 = fmaxf(rmax1, __shfl_xor_sync(0xffffffffu, rmax1, 1));
        rmax1 = fmaxf(rmax1, __shfl_xor_sync(0xffffffffu, rmax1, 2));
        if (tg == 0) {
            redm[m0r * 2 + wn]       = rmax0;
            redm[(m0r + 8) * 2 + wn] = rmax1;
        }
        __syncthreads();
        float mn0 = fmaxf(m0, fmaxf(redm[m0r * 2], redm[m0r * 2 + 1]));
        float mn1 = fmaxf(m1, fmaxf(redm[(m0r + 8) * 2], redm[(m0r + 8) * 2 + 1]));
        float alpha0 = __expf(m0 - mn0);
        float alpha1 = __expf(m1 - mn1);
        m0 = mn0; m1 = mn1;

        float rs0 = 0.f, rs1 = 0.f;
        #pragma unroll
        for (int j = 0; j < 4; j++) {
            float p00 = __expf(sacc[j][0] - mn0);
            float p01 = __expf(sacc[j][1] - mn0);
            float p10 = __expf(sacc[j][2] - mn1);
            float p11 = __expf(sacc[j][3] - mn1);
            rs0 += p00 + p01; rs1 += p10 + p11;
            int cu = (nb >> 1) + (j << 2) + tg;     // uint32 col (half pair)
            Ps[m0r * FQP + cu]       = h2u(__floats2half2_rn(p00, p01));
            Ps[(m0r + 8) * FQP + cu] = h2u(__floats2half2_rn(p10, p11));
        }
        rs0 += __shfl_xor_sync(0xffffffffu, rs0, 1);
        rs0 += __shfl_xor_sync(0xffffffffu, rs0, 2);
        rs1 += __shfl_xor_sync(0xffffffffu, rs1, 1);
        rs1 += __shfl_xor_sync(0xffffffffu, rs1, 2);
        if (tg == 0) {
            reds[m0r * 2 + wn]       = rs0;
            reds[(m0r + 8) * 2 + wn] = rs1;
        }
        #pragma unroll
        for (int j = 0; j < 4; j++) {
            accO[j][0] *= alpha0; accO[j][1] *= alpha0;
            accO[j][2] *= alpha1; accO[j][3] *= alpha1;
        }
        __syncthreads();
        l0 = l0 * alpha0 + reds[m0r * 2] + reds[m0r * 2 + 1];
        l1 = l1 * alpha1 + reds[(m0r + 8) * 2] + reds[(m0r + 8) * 2 + 1];

        #pragma unroll
        for (int ks = 0; ks < 4; ks++) {
            int kb = ks << 3;
            uint32_t af[4], bf[4][2];
            af[0] = Ps[m0r * FQP + kb + tg];
            af[1] = Ps[(m0r + 8) * FQP + kb + tg];
            af[2] = Ps[m0r * FQP + kb + 4 + tg];
            af[3] = Ps[(m0r + 8) * FQP + kb + 4 + tg];
            uint32_t rowa = vb_addr + (uint32_t)((ks * 16 + (lane & 15)) * (FQP * 4));
            #pragma unroll
            for (int j = 0; j < 4; j++) {
                int cb = nb + (j << 3);
                ldmatrix_x2_trans(bf[j][0], bf[j][1], rowa + cb * 2);
            }
            #pragma unroll
            for (int j = 0; j < 4; j++) mma_f16(accO[j], af, bf[j]);
        }
    }

    float inv0 = 1.0f / l0;
    float inv1 = 1.0f / l1;
    __half* out0 = g_ctx + ((size_t)b * T_ + t0 + m0r) * D_ + h * 64;
    __half* out1 = out0 + (size_t)8 * D_;
    #pragma unroll
    for (int j = 0; j < 4; j++) {
        int col = nb + (j << 3) + (tg << 1);
        *(__half2*)(out0 + col) = __floats2half2_rn(accO[j][0] * inv0, accO[j][1] * inv0);
        *(__half2*)(out1 + col) = __floats2half2_rn(accO[j][2] * inv1, accO[j][3] * inv1);
    }
}

// ---------------- launcher --------------------------------------------------
extern "C" void kernel_launch(void* const* d_in, const int* in_sizes, int n_in,
                              void* d_out, int out_size)
{
    const float* x    = (const float*)d_in[0];
    const float* ln1g = (const float*)d_in[1];
    const float* ln1b = (const float*)d_in[2];
    const float* ln2g = (const float*)d_in[3];
    const float* ln2b = (const float*)d_in[4];
    const float* Wq   = (const float*)d_in[5];
    const float* bq   = (const float*)d_in[6];
    const float* Wk   = (const float*)d_in[7];
    const float* bk   = (const float*)d_in[8];
    const float* Wv   = (const float*)d_in[9];
    const float* bv   = (const float*)d_in[10];
    const float* Wo   = (const float*)d_in[11];
    const float* bo   = (const float*)d_in[12];
    const float* W1   = (const float*)d_in[13];
    const float* b1   = (const float*)d_in[14];
    const float* W2   = (const float*)d_in[15];
    const float* b2   = (const float*)d_in[16];
    float* out = (float*)d_out;

    static __half* h_     = nullptr;
    static __half* qkv_   = nullptr;
    static float*  wcat_  = nullptr;
    static __half* wcatT_ = nullptr;
    static float*  bcat_  = nullptr;
    static __half* ctx_   = nullptr;
    static __half* ffa_   = nullptr;
    static __half* wrnd_  = nullptr;
    if (!h_) {   // pointer cache only — identical work every call
        cudaGetSymbolAddress((void**)&h_,     g_h);
        cudaGetSymbolAddress((void**)&qkv_,   g_qkv);
        cudaGetSymbolAddress((void**)&wcat_,  g_wcat);
        cudaGetSymbolAddress((void**)&wcatT_, g_wcatT);
        cudaGetSymbolAddress((void**)&bcat_,  g_bcat);
        cudaGetSymbolAddress((void**)&ctx_,   g_ctx);
        cudaGetSymbolAddress((void**)&ffa_,   g_ffa);
        cudaGetSymbolAddress((void**)&wrnd_,  g_wrndh);
        cudaFuncSetAttribute(flash_attn_kernel,
                             cudaFuncAttributeMaxDynamicSharedMemorySize, FLASH_SMEM_BYTES);
    }
    __half* woT = wrnd_;
    __half* w1T = wrnd_ + (size_t)D_ * D_;
    __half* w2T = wrnd_ + (size_t)D_ * D_ + (size_t)D_ * FF_;

    // 1) weight prep: repack, then transpose+halve everything to [N][K]
    repack_kernel<<<(D_ * TD3_ + 255) / 256, 256>>>(Wq, Wk, Wv, bq, bk, bv);
    transTh_kernel<<<dim3(TD3_ / 32, D_ / 32), 256>>>(wcat_, wcatT_, D_, TD3_);
    transTh_kernel<<<dim3(D_ / 32, D_ / 32), 256>>>(Wo, woT, D_, D_);
    transTh_kernel<<<dim3(FF_ / 32, D_ / 32), 256>>>(W1, w1T, D_, FF_);
    transTh_kernel<<<dim3(D_ / 32, FF_ / 32), 256>>>(W2, w2T, FF_, D_);
    // 2) ln1 -> h (half)
    ln_kernel<<<BT_, 256>>>(x, ln1g, ln1b, h_);
    // 3) QKV = h @ Wcat + bcat -> half
    hgemm_kernel<1, 1><<<dim3(TD3_ / 128, BT_ / 128), 256>>>(
        h_, wcatT_, qkv_, bcat_, nullptr, BT_, TD3_, D_);
    // 4-6) fused attention -> ctx (half)
    flash_attn_kernel<<<dim3(16, B_ * H_), 256, FLASH_SMEM_BYTES>>>();
    // 7) X1 = x + ctx @ Wo + bo -> out (fp32)
    hgemm_kernel<5, 0><<<dim3(D_ / 128, BT_ / 128), 256>>>(
        ctx_, woT, out, bo, x, BT_, D_, D_);
    // 8) ln2 -> h (half)
    ln_kernel<<<BT_, 256>>>(out, ln2g, ln2b, h_);
    // 9) ffa = gelu(h @ W1 + b1) -> half
    hgemm_kernel<3, 1><<<dim3(FF_ / 128, BT_ / 128), 256>>>(
        h_, w1T, ffa_, b1, nullptr, BT_, FF_, D_);
    // 10) out = X1 + ffa @ W2 + b2 -> fp32
    hgemm_kernel<5, 0><<<dim3(D_ / 128, BT_ / 128), 256>>>(
        ffa_, w2T, out, b2, out, BT_, D_, FF_);
}

// round 16
// speedup vs baseline: 1.8085x; 1.0054x over previous
#include <cuda_runtime.h>
#include <cuda_fp16.h>
#include <cstdint>
#include <cstddef>
#include <cstring>

#define B_  8
#define T_  1024
#define D_  1024
#define H_  16
#define HD_ 64
#define FF_ 4096
#define BT_ (B_*T_)            // 8192
#define TD3_ (3*D_)            // 3072

// ---------------- scratch (device globals: allocation-guard-safe) ----------
__device__ __half g_h[(size_t)BT_ * D_];         // 16 MB (ln output, half)
__device__ __half g_qkv[(size_t)BT_ * TD3_];     // 48 MB (QKV, half)
__device__ float  g_wcat[(size_t)D_ * TD3_];     // 12 MB (staging fp32)
__device__ __half g_wcatT[(size_t)TD3_ * D_];    // 6 MB  [N][K] half
__device__ float  g_bcat[TD3_];
__device__ __half g_ctx[(size_t)BT_ * D_];       // 16 MB (flash out, half)
__device__ __half g_ffa[(size_t)BT_ * FF_];      // 64 MB (gelu out, half)
__device__ __half g_wrndh[(size_t)D_*D_ + (size_t)D_*FF_ + (size_t)FF_*D_]; // 18 MB

// ---------------- helpers ---------------------------------------------------
__device__ __forceinline__ float geluf(float x) {
    return 0.5f * x * (1.0f + erff(x * 0.70710678118654752f));
}
__device__ __forceinline__ uint32_t h2u(__half2 v) {
    uint32_t r; memcpy(&r, &v, 4); return r;
}
__device__ __forceinline__ void mma_f16(float c[4], const uint32_t a[4], const uint32_t b[2]) {
    asm volatile(
        "mma.sync.aligned.m16n8k16.row.col.f32.f16.f16.f32 "
        "{%0,%1,%2,%3}, {%4,%5,%6,%7}, {%8,%9}, {%0,%1,%2,%3};"
        : "+f"(c[0]), "+f"(c[1]), "+f"(c[2]), "+f"(c[3])
        : "r"(a[0]), "r"(a[1]), "r"(a[2]), "r"(a[3]), "r"(b[0]), "r"(b[1]));
}
__device__ __forceinline__ void ldmx4(uint32_t& r0, uint32_t& r1, uint32_t& r2, uint32_t& r3,
                                      uint32_t saddr) {
    asm volatile("ldmatrix.sync.aligned.m8n8.x4.shared.b16 {%0,%1,%2,%3}, [%4];"
                 : "=r"(r0), "=r"(r1), "=r"(r2), "=r"(r3) : "r"(saddr));
}
__device__ __forceinline__ void ldmx4_trans(uint32_t& r0, uint32_t& r1, uint32_t& r2, uint32_t& r3,
                                            uint32_t saddr) {
    asm volatile("ldmatrix.sync.aligned.m8n8.x4.trans.shared.b16 {%0,%1,%2,%3}, [%4];"
                 : "=r"(r0), "=r"(r1), "=r"(r2), "=r"(r3) : "r"(saddr));
}
__device__ __forceinline__ void cp_async16(void* sptr, const void* gptr) {
    uint32_t s = (uint32_t)__cvta_generic_to_shared(sptr);
    asm volatile("cp.async.cg.shared.global [%0], [%1], 16;" :: "r"(s), "l"(gptr));
}
#define CP_COMMIT() asm volatile("cp.async.commit_group;")
#define CP_WAIT0()  asm volatile("cp.async.wait_group 0;")

// ---------------- weight repack: Wq/Wk/Wv [H,D,HD] -> Wcat fp32 [D, 3D] -----
__global__ __launch_bounds__(256) void repack_kernel(
    const float* __restrict__ Wq, const float* __restrict__ Wk, const float* __restrict__ Wv,
    const float* __restrict__ bq, const float* __restrict__ bk, const float* __restrict__ bv)
{
    int t = blockIdx.x * blockDim.x + threadIdx.x;
    if (t >= D_ * TD3_) return;
    int d = t / TD3_;
    int n = t - d * TD3_;
    int part = n >> 10;
    int m = n & (D_ - 1);
    int h = m >> 6, e = m & 63;
    const float* W = (part == 0) ? Wq : (part == 1) ? Wk : Wv;
    g_wcat[t] = W[((size_t)h * D_ + d) * HD_ + e];
    if (d == 0) {
        const float* bb = (part == 0) ? bq : (part == 1) ? bk : bv;
        g_bcat[n] = bb[m];
    }
}

// ---------------- tiled transpose fp32[R][C] -> half[C][R] ------------------
__global__ __launch_bounds__(256) void transTh_kernel(
    const float* __restrict__ src, __half* __restrict__ dst, int R, int C)
{
    __shared__ float tile[32][33];
    int bx = blockIdx.x * 32, by = blockIdx.y * 32;
    int tx = threadIdx.x & 31, ty = threadIdx.x >> 5;   // 32 x 8
    #pragma unroll
    for (int i = 0; i < 32; i += 8)
        tile[ty + i][tx] = src[(size_t)(by + ty + i) * C + bx + tx];
    __syncthreads();
    #pragma unroll
    for (int i = 0; i < 32; i += 8)
        dst[(size_t)(bx + ty + i) * R + by + tx] = __float2half(tile[tx][ty + i]);
}

// ---------------- layernorm: fp32 in -> half out ----------------------------
__global__ __launch_bounds__(256) void ln_kernel(
    const float* __restrict__ x, const float* __restrict__ g,
    const float* __restrict__ bta, __half* __restrict__ y)
{
    int row = blockIdx.x;
    int tid = threadIdx.x;
    const float4* xr = (const float4*)(x + (size_t)row * D_);
    float4 v = xr[tid];
    float s  = v.x + v.y + v.z + v.w;
    float ss = v.x*v.x + v.y*v.y + v.z*v.z + v.w*v.w;
    __shared__ float sh_s[8], sh_ss[8];
    #pragma unroll
    for (int o = 16; o > 0; o >>= 1) {
        s  += __shfl_down_sync(0xffffffffu, s,  o);
        ss += __shfl_down_sync(0xffffffffu, ss, o);
    }
    if ((tid & 31) == 0) { sh_s[tid >> 5] = s; sh_ss[tid >> 5] = ss; }
    __syncthreads();
    float S = 0.f, SS = 0.f;
    #pragma unroll
    for (int i = 0; i < 8; i++) { S += sh_s[i]; SS += sh_ss[i]; }
    float mu  = S * (1.0f / D_);
    float var = SS * (1.0f / D_) - mu * mu;
    float inv = rsqrtf(var + 1e-5f);
    float4 g4 = ((const float4*)g)[tid];
    float4 b4 = ((const float4*)bta)[tid];
    __half2 o0 = __floats2half2_rn((v.x - mu) * inv * g4.x + b4.x,
                                   (v.y - mu) * inv * g4.y + b4.y);
    __half2 o1 = __floats2half2_rn((v.z - mu) * inv * g4.z + b4.z,
                                   (v.w - mu) * inv * g4.w + b4.w);
    __half2* yp = (__half2*)(y + (size_t)row * D_) + tid * 2;
    yp[0] = o0; yp[1] = o1;
}

// ---------------- fp16 tensor-core GEMM 128x128, K-stage 32, 2-stage --------
// (unchanged from R15: ldmatrix.x4 fragments)
template <int EPI, int OUTH>
__global__ __launch_bounds__(256, 2) void hgemm_kernel(
    const __half* __restrict__ A, const __half* __restrict__ Bt,
    void* __restrict__ Cv, const float* __restrict__ bias,
    const float* __restrict__ res, int M, int N, int K)
{
    __shared__ uint32_t As[2][128][20];
    __shared__ uint32_t Bs[2][128][20];
    int tid = threadIdx.x;
    int lane = tid & 31, warp = tid >> 5;
    int g = lane >> 2, tg = lane & 3;
    int mw = (warp & 3) << 5;
    int nw = (warp >> 2) << 6;
    int bm = blockIdx.y, bn = blockIdx.x;
    const __half* Ab = A  + (size_t)bm * 128 * K;
    const __half* Bb = Bt + (size_t)bn * 128 * K;

    float acc[2][8][4];
    #pragma unroll
    for (int mi = 0; mi < 2; mi++)
        #pragma unroll
        for (int j = 0; j < 8; j++)
            #pragma unroll
            for (int q = 0; q < 4; q++) acc[mi][j][q] = 0.f;

    int lrow = tid >> 1;
    int lseg = (tid & 1) << 3;

    uint32_t as0 = (uint32_t)__cvta_generic_to_shared(&As[0][0][0]);
    uint32_t bs0 = (uint32_t)__cvta_generic_to_shared(&Bs[0][0][0]);
    uint32_t aoff[2];
    #pragma unroll
    for (int mi = 0; mi < 2; mi++) {
        int row = mw + (mi << 4) + ((lane >> 3) & 1) * 8 + (lane & 7);
        int col = (lane >> 4) << 2;
        aoff[mi] = (uint32_t)((row * 20 + col) * 4);
    }
    uint32_t boff[4];
    #pragma unroll
    for (int jj = 0; jj < 4; jj++) {
        int row = nw + (jj << 4) + ((lane >> 4) << 3) + (lane & 7);
        int col = ((lane >> 3) & 1) << 2;
        boff[jj] = (uint32_t)((row * 20 + col) * 4);
    }
    const uint32_t TILE_BYTES = 128 * 20 * 4;

    cp_async16(&As[0][lrow][lseg],     Ab + (size_t)lrow * K + (lseg << 1));
    cp_async16(&As[0][lrow][lseg + 4], Ab + (size_t)lrow * K + (lseg << 1) + 8);
    cp_async16(&Bs[0][lrow][lseg],     Bb + (size_t)lrow * K + (lseg << 1));
    cp_async16(&Bs[0][lrow][lseg + 4], Bb + (size_t)lrow * K + (lseg << 1) + 8);
    CP_COMMIT();

    int nk = K >> 5;
    for (int it = 0; it < nk; it++) {
        int buf = it & 1;
        CP_WAIT0();
        __syncthreads();
        if (it + 1 < nk) {
            int kt = (it + 1) << 5;
            int nb2 = buf ^ 1;
            cp_async16(&As[nb2][lrow][lseg],     Ab + (size_t)lrow * K + kt + (lseg << 1));
            cp_async16(&As[nb2][lrow][lseg + 4], Ab + (size_t)lrow * K + kt + (lseg << 1) + 8);
            cp_async16(&Bs[nb2][lrow][lseg],     Bb + (size_t)lrow * K + kt + (lseg << 1));
            cp_async16(&Bs[nb2][lrow][lseg + 4], Bb + (size_t)lrow * K + kt + (lseg << 1) + 8);
            CP_COMMIT();
        }
        uint32_t ab = as0 + buf * TILE_BYTES;
        uint32_t bb2 = bs0 + buf * TILE_BYTES;
        #pragma unroll
        for (int ks = 0; ks < 2; ks++) {
            uint32_t kbyte = (uint32_t)(ks * 32);
            uint32_t af[2][4], bf[8][2];
            #pragma unroll
            for (int mi = 0; mi < 2; mi++)
                ldmx4(af[mi][0], af[mi][1], af[mi][2], af[mi][3],
                      ab + aoff[mi] + kbyte);
            #pragma unroll
            for (int jj = 0; jj < 4; jj++)
                ldmx4(bf[2*jj][0], bf[2*jj][1], bf[2*jj+1][0], bf[2*jj+1][1],
                      bb2 + boff[jj] + kbyte);
            #pragma unroll
            for (int mi = 0; mi < 2; mi++)
                #pragma unroll
                for (int j = 0; j < 8; j++)
                    mma_f16(acc[mi][j], af[mi], bf[j]);
        }
    }

    #pragma unroll
    for (int mi = 0; mi < 2; mi++) {
        int r0 = bm * 128 + mw + (mi << 4) + g;
        int r1 = r0 + 8;
        #pragma unroll
        for (int j = 0; j < 8; j++) {
            int c = bn * 128 + nw + (j << 3) + (tg << 1);
            float v0 = acc[mi][j][0], v1 = acc[mi][j][1];
            float v2 = acc[mi][j][2], v3 = acc[mi][j][3];
            if (EPI & 1) {
                float2 bv = *(const float2*)(bias + c);
                v0 += bv.x; v1 += bv.y; v2 += bv.x; v3 += bv.y;
            }
            if (EPI & 2) {
                v0 = geluf(v0); v1 = geluf(v1);
                v2 = geluf(v2); v3 = geluf(v3);
            }
            if (EPI & 4) {
                float2 ra = *(const float2*)(res + (size_t)r0 * N + c);
                float2 rb = *(const float2*)(res + (size_t)r1 * N + c);
                v0 += ra.x; v1 += ra.y; v2 += rb.x; v3 += rb.y;
            }
            if (OUTH) {
                __half* Ch = (__half*)Cv;
                *(__half2*)(Ch + (size_t)r0 * N + c) = __floats2half2_rn(v0, v1);
                *(__half2*)(Ch + (size_t)r1 * N + c) = __floats2half2_rn(v2, v3);
            } else {
                float* Cf = (float*)Cv;
                float2 w0 = { v0, v1 }, w1 = { v2, v3 };
                *(float2*)(Cf + (size_t)r0 * N + c) = w0;
                *(float2*)(Cf + (size_t)r1 * N + c) = w1;
            }
        }
    }
}

// ---------------- flash attention, fp16 mma + full ldmatrix -----------------
// Block: (bh, 64 q-rows). 8 warps 4(m)x2(n), warp tile 16x32.
// Q/K/P row-major half pitch FQP=36 u32; fragments via ldmatrix.x4;
// V B-fragments via ldmatrix.x4.trans on row-major V. Softmax fp32.
#define FQP 36
#define FLASH_SMEM_U32 (6*64*FQP + 256)
#define FLASH_SMEM_BYTES (FLASH_SMEM_U32 * 4)

__global__ __launch_bounds__(256, 2) void flash_attn_kernel()
{
    extern __shared__ uint32_t usm[];
    uint32_t* Qs = usm;                    // [64][FQP]
    uint32_t* Ks = Qs + 64 * FQP;          // [2][64][FQP]
    uint32_t* Vs = Ks + 2 * 64 * FQP;      // [2][64][FQP]
    uint32_t* Ps = Vs + 2 * 64 * FQP;      // [64][FQP]
    float* redm  = (float*)(Ps + 64 * FQP); // [128]
    float* reds  = redm + 128;              // [128]

    int bh = blockIdx.y;
    int b = bh >> 4, h = bh & 15;
    int t0 = blockIdx.x * 64;
    int tid = threadIdx.x;
    int lane = tid & 31, warp = tid >> 5;
    int g = lane >> 2, tg = lane & 3;
    int wm = warp & 3, wn = warp >> 2;
    int m0r = (wm << 4) + g;
    int nb  = wn << 5;

    // ldmatrix per-thread byte offsets (GEMM-validated mappings, pitch FQP)
    // A-frag (16x16 at row base wm*16): m8-blocks x k8-halves
    uint32_t a_off;
    {
        int row = (wm << 4) + ((lane >> 3) & 1) * 8 + (lane & 7);
        int col = (lane >> 4) << 2;
        a_off = (uint32_t)((row * FQP + col) * 4);
    }
    // K B-frag (2 x 16 n-rows from nb): same pattern as GEMM boff
    uint32_t k_off[2];
    #pragma unroll
    for (int jj = 0; jj < 2; jj++) {
        int row = nb + (jj << 4) + ((lane >> 4) << 3) + (lane & 7);
        int col = ((lane >> 3) & 1) << 2;
        k_off[jj] = (uint32_t)((row * FQP + col) * 4);
    }
    // V x4.trans (per jp in {0,1}): matrices (k0,n0),(k8,n0),(k0,n8),(k8,n8)
    // lane i=lane>>3 selects matrix; r=lane&7 source row within k8-block.
    uint32_t v_off[2];
    #pragma unroll
    for (int jp = 0; jp < 2; jp++) {
        int row = (((lane >> 3) & 1) << 3) + (lane & 7);      // k-block row
        int colh = nb + (jp << 4) + ((lane >> 4) << 3);       // half col
        v_off[jp] = (uint32_t)(row * FQP * 4 + colh * 2);
    }

    const __half* qbase = g_qkv + ((size_t)b * T_) * TD3_ + h * 64;
    int lrow = tid >> 3;              // 0..31 (+32)
    int lch  = tid & 7;               // 16B chunk 0..7

    #pragma unroll
    for (int i = 0; i < 2; i++) {
        int row = lrow + i * 32;
        cp_async16(&Qs[row * FQP + lch * 4], qbase + (size_t)(t0 + row) * TD3_ + lch * 8);
    }
    CP_COMMIT();
    #pragma unroll
    for (int i = 0; i < 2; i++) {
        int row = lrow + i * 32;
        cp_async16(&Ks[row * FQP + lch * 4], qbase + 1024 + (size_t)row * TD3_ + lch * 8);
        cp_async16(&Vs[row * FQP + lch * 4], qbase + 2048 + (size_t)row * TD3_ + lch * 8);
    }
    CP_COMMIT();

    uint32_t qs_addr = (uint32_t)__cvta_generic_to_shared(Qs);
    uint32_t ps_addr = (uint32_t)__cvta_generic_to_shared(Ps);

    float accO[4][4];
    #pragma unroll
    for (int j = 0; j < 4; j++)
        #pragma unroll
        for (int q = 0; q < 4; q++) accO[j][q] = 0.f;
    float m0 = -3.0e38f, m1 = -3.0e38f, l0 = 0.f, l1 = 0.f;

    for (int st = 0; st < 16; st++) {
        int buf = st & 1;
        uint32_t* Kb = Ks + buf * 64 * FQP;
        uint32_t* Vb = Vs + buf * 64 * FQP;
        uint32_t kb_addr = (uint32_t)__cvta_generic_to_shared(Kb);
        uint32_t vb_addr = (uint32_t)__cvta_generic_to_shared(Vb);
        CP_WAIT0();
        __syncthreads();
        if (st + 1 < 16) {
            int s1 = (st + 1) * 64;
            uint32_t* Kn = Ks + (buf ^ 1) * 64 * FQP;
            uint32_t* Vn = Vs + (buf ^ 1) * 64 * FQP;
            #pragma unroll
            for (int i = 0; i < 2; i++) {
                int row = lrow + i * 32;
                cp_async16(&Kn[row * FQP + lch * 4], qbase + 1024 + (size_t)(s1 + row) * TD3_ + lch * 8);
                cp_async16(&Vn[row * FQP + lch * 4], qbase + 2048 + (size_t)(s1 + row) * TD3_ + lch * 8);
            }
            CP_COMMIT();
        }

        // S = Q K^T  (4 k16 steps over e=64)
        float sacc[4][4];
        #pragma unroll
        for (int j = 0; j < 4; j++)
            #pragma unroll
            for (int q = 0; q < 4; q++) sacc[j][q] = 0.f;
        #pragma unroll
        for (int ks = 0; ks < 4; ks++) {
            uint32_t kbyte = (uint32_t)(ks * 32);   // 8 u32 = 32 B
            uint32_t af[4], bf[4][2];
            ldmx4(af[0], af[1], af[2], af[3], qs_addr + a_off + kbyte);
            #pragma unroll
            for (int jj = 0; jj < 2; jj++)
                ldmx4(bf[2*jj][0], bf[2*jj][1], bf[2*jj+1][0], bf[2*jj+1][1],
                      kb_addr + k_off[jj] + kbyte);
            #pragma unroll
            for (int j = 0; j < 4; j++) mma_f16(sacc[j], af, bf[j]);
        }

        // scale + row max
        float rmax0 = -3.0e38f, rmax1 = -3.0e38f;
        #pragma unroll
        for (int j = 0; j < 4; j++) {
            #pragma unroll
            for (int q = 0; q < 4; q++) sacc[j][q] *= 0.125f;
            rmax0 = fmaxf(rmax0, fmaxf(sacc[j][0], sacc[j][1]));
            rmax1 = fmaxf(rmax1, fmaxf(sacc[j][2], sacc[j][3]));
        }
        rmax0 = fmaxf(rmax0, __shfl_xor_sync(0xffffffffu, rmax0, 1));
        rmax0 = fmaxf(rmax0, __shfl_xor_sync(0xffffffffu, rmax0, 2));
        rmax1 = fmaxf(rmax1, __shfl_xor_sync(0xffffffffu, rmax1, 1));
        rmax1 = fmaxf(rmax1, __shfl_xor_sync(0xffffffffu, rmax1, 2));
        if (tg == 0) {
            redm[m0r * 2 + wn]       = rmax0;
            redm[(m0r + 8) * 2 + wn] = rmax1;
        }
        __syncthreads();
        float mn0 = fmaxf(m0, fmaxf(redm[m0r * 2], redm[m0r * 2 + 1]));
        float mn1 = fmaxf(m1, fmaxf(redm[(m0r + 8) * 2], redm[(m0r + 8) * 2 + 1]));
        float alpha0 = __expf(m0 - mn0);
        float alpha1 = __expf(m1 - mn1);
        m0 = mn0; m1 = mn1;

        // P = exp(S - m), store half pairs (canonical row-major layout)
        float rs0 = 0.f, rs1 = 0.f;
        #pragma unroll
        for (int j = 0; j < 4; j++) {
            float p00 = __expf(sacc[j][0] - mn0);
            float p01 = __expf(sacc[j][1] - mn0);
            float p10 = __expf(sacc[j][2] - mn1);
            float p11 = __expf(sacc[j][3] - mn1);
            rs0 += p00 + p01; rs1 += p10 + p11;
            int cu = (nb >> 1) + (j << 2) + tg;     // uint32 col (half pair)
            Ps[m0r * FQP + cu]       = h2u(__floats2half2_rn(p00, p01));
            Ps[(m0r + 8) * FQP + cu] = h2u(__floats2half2_rn(p10, p11));
        }
        rs0 += __shfl_xor_sync(0xffffffffu, rs0, 1);
        rs0 += __shfl_xor_sync(0xffffffffu, rs0, 2);
        rs1 += __shfl_xor_sync(0xffffffffu, rs1, 1);
        rs1 += __shfl_xor_sync(0xffffffffu, rs1, 2);
        if (tg == 0) {
            reds[m0r * 2 + wn]       = rs0;
            reds[(m0r + 8) * 2 + wn] = rs1;
        }
        #pragma unroll
        for (int j = 0; j < 4; j++) {
            accO[j][0] *= alpha0; accO[j][1] *= alpha0;
            accO[j][2] *= alpha1; accO[j][3] *= alpha1;
        }
        __syncthreads();
        l0 = l0 * alpha0 + reds[m0r * 2] + reds[m0r * 2 + 1];
        l1 = l1 * alpha1 + reds[(m0r + 8) * 2] + reds[(m0r + 8) * 2 + 1];

        // O += P @ V  (A via ldmx4 on Ps; B via ldmx4.trans on row-major V)
        #pragma unroll
        for (int ks = 0; ks < 4; ks++) {
            uint32_t kbyte = (uint32_t)(ks * 32);
            uint32_t vrow  = (uint32_t)(ks * 16 * FQP * 4);
            uint32_t af[4], bf[4][2];
            ldmx4(af[0], af[1], af[2], af[3], ps_addr + a_off + kbyte);
            #pragma unroll
            for (int jp = 0; jp < 2; jp++)
                ldmx4_trans(bf[2*jp][0], bf[2*jp][1], bf[2*jp+1][0], bf[2*jp+1][1],
                            vb_addr + v_off[jp] + vrow);
            #pragma unroll
            for (int j = 0; j < 4; j++) mma_f16(accO[j], af, bf[j]);
        }
    }

    float inv0 = 1.0f / l0;
    float inv1 = 1.0f / l1;
    __half* out0 = g_ctx + ((size_t)b * T_ + t0 + m0r) * D_ + h * 64;
    __half* out1 = out0 + (size_t)8 * D_;
    #pragma unroll
    for (int j = 0; j < 4; j++) {
        int col = nb + (j << 3) + (tg << 1);
        *(__half2*)(out0 + col) = __floats2half2_rn(accO[j][0] * inv0, accO[j][1] * inv0);
        *(__half2*)(out1 + col) = __floats2half2_rn(accO[j][2] * inv1, accO[j][3] * inv1);
    }
}

// ---------------- launcher --------------------------------------------------
extern "C" void kernel_launch(void* const* d_in, const int* in_sizes, int n_in,
                              void* d_out, int out_size)
{
    const float* x    = (const float*)d_in[0];
    const float* ln1g = (const float*)d_in[1];
    const float* ln1b = (const float*)d_in[2];
    const float* ln2g = (const float*)d_in[3];
    const float* ln2b = (const float*)d_in[4];
    const float* Wq   = (const float*)d_in[5];
    const float* bq   = (const float*)d_in[6];
    const float* Wk   = (const float*)d_in[7];
    const float* bk   = (const float*)d_in[8];
    const float* Wv   = (const float*)d_in[9];
    const float* bv   = (const float*)d_in[10];
    const float* Wo   = (const float*)d_in[11];
    const float* bo   = (const float*)d_in[12];
    const float* W1   = (const float*)d_in[13];
    const float* b1   = (const float*)d_in[14];
    const float* W2   = (const float*)d_in[15];
    const float* b2   = (const float*)d_in[16];
    float* out = (float*)d_out;

    static __half* h_     = nullptr;
    static __half* qkv_   = nullptr;
    static float*  wcat_  = nullptr;
    static __half* wcatT_ = nullptr;
    static float*  bcat_  = nullptr;
    static __half* ctx_   = nullptr;
    static __half* ffa_   = nullptr;
    static __half* wrnd_  = nullptr;
    if (!h_) {   // pointer cache only — identical work every call
        cudaGetSymbolAddress((void**)&h_,     g_h);
        cudaGetSymbolAddress((void**)&qkv_,   g_qkv);
        cudaGetSymbolAddress((void**)&wcat_,  g_wcat);
        cudaGetSymbolAddress((void**)&wcatT_, g_wcatT);
        cudaGetSymbolAddress((void**)&bcat_,  g_bcat);
        cudaGetSymbolAddress((void**)&ctx_,   g_ctx);
        cudaGetSymbolAddress((void**)&ffa_,   g_ffa);
        cudaGetSymbolAddress((void**)&wrnd_,  g_wrndh);
        cudaFuncSetAttribute(flash_attn_kernel,
                             cudaFuncAttributeMaxDynamicSharedMemorySize, FLASH_SMEM_BYTES);
    }
    __half* woT = wrnd_;
    __half* w1T = wrnd_ + (size_t)D_ * D_;
    __half* w2T = wrnd_ + (size_t)D_ * D_ + (size_t)D_ * FF_;

    // 1) weight prep: repack, then transpose+halve everything to [N][K]
    repack_kernel<<<(D_ * TD3_ + 255) / 256, 256>>>(Wq, Wk, Wv, bq, bk, bv);
    transTh_kernel<<<dim3(TD3_ / 32, D_ / 32), 256>>>(wcat_, wcatT_, D_, TD3_);
    transTh_kernel<<<dim3(D_ / 32, D_ / 32), 256>>>(Wo, woT, D_, D_);
    transTh_kernel<<<dim3(FF_ / 32, D_ / 32), 256>>>(W1, w1T, D_, FF_);
    transTh_kernel<<<dim3(D_ / 32, FF_ / 32), 256>>>(W2, w2T, FF_, D_);
    // 2) ln1 -> h (half)
    ln_kernel<<<BT_, 256>>>(x, ln1g, ln1b, h_);
    // 3) QKV = h @ Wcat + bcat -> half
    hgemm_kernel<1, 1><<<dim3(TD3_ / 128, BT_ / 128), 256>>>(
        h_, wcatT_, qkv_, bcat_, nullptr, BT_, TD3_, D_);
    // 4-6) fused attention -> ctx (half)
    flash_attn_kernel<<<dim3(16, B_ * H_), 256, FLASH_SMEM_BYTES>>>();
    // 7) X1 = x + ctx @ Wo + bo -> out (fp32)
    hgemm_kernel<5, 0><<<dim3(D_ / 128, BT_ / 128), 256>>>(
        ctx_, woT, out, bo, x, BT_, D_, D_);
    // 8) ln2 -> h (half)
    ln_kernel<<<BT_, 256>>>(out, ln2g, ln2b, h_);
    // 9) ffa = gelu(h @ W1 + b1) -> half
    hgemm_kernel<3, 1><<<dim3(FF_ / 128, BT_ / 128), 256>>>(
        h_, w1T, ffa_, b1, nullptr, BT_, FF_, D_);
    // 10) out = X1 + ffa @ W2 + b2 -> fp32
    hgemm_kernel<5, 0><<<dim3(D_ / 128, BT_ / 128), 256>>>(
        ffa_, w2T, out, b2, out, BT_, D_, FF_);
}

// round 17
// speedup vs baseline: 1.8149x; 1.0035x over previous
#include <cuda_runtime.h>
#include <cuda_fp16.h>
#include <cstdint>
#include <cstddef>
#include <cstring>

#define B_  8
#define T_  1024
#define D_  1024
#define H_  16
#define HD_ 64
#define FF_ 4096
#define BT_ (B_*T_)            // 8192
#define TD3_ (3*D_)            // 3072

// ---------------- scratch (device globals: allocation-guard-safe) ----------
__device__ __half g_h[(size_t)BT_ * D_];         // 16 MB (ln output, half)
__device__ __half g_qkv[(size_t)BT_ * TD3_];     // 48 MB (QKV, half)
__device__ float  g_wcat[(size_t)D_ * TD3_];     // 12 MB (staging fp32)
__device__ __half g_wcatT[(size_t)TD3_ * D_];    // 6 MB  [N][K] half
__device__ float  g_bcat[TD3_];
__device__ __half g_ctx[(size_t)BT_ * D_];       // 16 MB (flash out, half)
__device__ __half g_ffa[(size_t)BT_ * FF_];      // 64 MB (gelu out, half)
__device__ __half g_wrndh[(size_t)D_*D_ + (size_t)D_*FF_ + (size_t)FF_*D_]; // 18 MB

// ---------------- helpers ---------------------------------------------------
__device__ __forceinline__ float geluf(float x) {
    return 0.5f * x * (1.0f + erff(x * 0.70710678118654752f));
}
__device__ __forceinline__ uint32_t h2u(__half2 v) {
    uint32_t r; memcpy(&r, &v, 4); return r;
}
__device__ __forceinline__ void mma_f16(float c[4], const uint32_t a[4], const uint32_t b[2]) {
    asm volatile(
        "mma.sync.aligned.m16n8k16.row.col.f32.f16.f16.f32 "
        "{%0,%1,%2,%3}, {%4,%5,%6,%7}, {%8,%9}, {%0,%1,%2,%3};"
        : "+f"(c[0]), "+f"(c[1]), "+f"(c[2]), "+f"(c[3])
        : "r"(a[0]), "r"(a[1]), "r"(a[2]), "r"(a[3]), "r"(b[0]), "r"(b[1]));
}
__device__ __forceinline__ void ldmx4(uint32_t& r0, uint32_t& r1, uint32_t& r2, uint32_t& r3,
                                      uint32_t saddr) {
    asm volatile("ldmatrix.sync.aligned.m8n8.x4.shared.b16 {%0,%1,%2,%3}, [%4];"
                 : "=r"(r0), "=r"(r1), "=r"(r2), "=r"(r3) : "r"(saddr));
}
__device__ __forceinline__ void ldmx4_trans(uint32_t& r0, uint32_t& r1, uint32_t& r2, uint32_t& r3,
                                            uint32_t saddr) {
    asm volatile("ldmatrix.sync.aligned.m8n8.x4.trans.shared.b16 {%0,%1,%2,%3}, [%4];"
                 : "=r"(r0), "=r"(r1), "=r"(r2), "=r"(r3) : "r"(saddr));
}
__device__ __forceinline__ void cp_async16(void* sptr, const void* gptr) {
    uint32_t s = (uint32_t)__cvta_generic_to_shared(sptr);
    asm volatile("cp.async.cg.shared.global [%0], [%1], 16;" :: "r"(s), "l"(gptr));
}
__device__ __forceinline__ void cp_async16_s(uint32_t saddr, const void* gptr) {
    asm volatile("cp.async.cg.shared.global [%0], [%1], 16;" :: "r"(saddr), "l"(gptr));
}
#define CP_COMMIT() asm volatile("cp.async.commit_group;")
#define CP_WAIT0()  asm volatile("cp.async.wait_group 0;")
#define CP_WAIT1()  asm volatile("cp.async.wait_group 1;")

// ---------------- weight repack: Wq/Wk/Wv [H,D,HD] -> Wcat fp32 [D, 3D] -----
__global__ __launch_bounds__(256) void repack_kernel(
    const float* __restrict__ Wq, const float* __restrict__ Wk, const float* __restrict__ Wv,
    const float* __restrict__ bq, const float* __restrict__ bk, const float* __restrict__ bv)
{
    int t = blockIdx.x * blockDim.x + threadIdx.x;
    if (t >= D_ * TD3_) return;
    int d = t / TD3_;
    int n = t - d * TD3_;
    int part = n >> 10;
    int m = n & (D_ - 1);
    int h = m >> 6, e = m & 63;
    const float* W = (part == 0) ? Wq : (part == 1) ? Wk : Wv;
    g_wcat[t] = W[((size_t)h * D_ + d) * HD_ + e];
    if (d == 0) {
        const float* bb = (part == 0) ? bq : (part == 1) ? bk : bv;
        g_bcat[n] = bb[m];
    }
}

// ---------------- tiled transpose fp32[R][C] -> half[C][R] ------------------
__global__ __launch_bounds__(256) void transTh_kernel(
    const float* __restrict__ src, __half* __restrict__ dst, int R, int C)
{
    __shared__ float tile[32][33];
    int bx = blockIdx.x * 32, by = blockIdx.y * 32;
    int tx = threadIdx.x & 31, ty = threadIdx.x >> 5;   // 32 x 8
    #pragma unroll
    for (int i = 0; i < 32; i += 8)
        tile[ty + i][tx] = src[(size_t)(by + ty + i) * C + bx + tx];
    __syncthreads();
    #pragma unroll
    for (int i = 0; i < 32; i += 8)
        dst[(size_t)(bx + ty + i) * R + by + tx] = __float2half(tile[tx][ty + i]);
}

// ---------------- layernorm: fp32 in -> half out ----------------------------
__global__ __launch_bounds__(256) void ln_kernel(
    const float* __restrict__ x, const float* __restrict__ g,
    const float* __restrict__ bta, __half* __restrict__ y)
{
    int row = blockIdx.x;
    int tid = threadIdx.x;
    const float4* xr = (const float4*)(x + (size_t)row * D_);
    float4 v = xr[tid];
    float s  = v.x + v.y + v.z + v.w;
    float ss = v.x*v.x + v.y*v.y + v.z*v.z + v.w*v.w;
    __shared__ float sh_s[8], sh_ss[8];
    #pragma unroll
    for (int o = 16; o > 0; o >>= 1) {
        s  += __shfl_down_sync(0xffffffffu, s,  o);
        ss += __shfl_down_sync(0xffffffffu, ss, o);
    }
    if ((tid & 31) == 0) { sh_s[tid >> 5] = s; sh_ss[tid >> 5] = ss; }
    __syncthreads();
    float S = 0.f, SS = 0.f;
    #pragma unroll
    for (int i = 0; i < 8; i++) { S += sh_s[i]; SS += sh_ss[i]; }
    float mu  = S * (1.0f / D_);
    float var = SS * (1.0f / D_) - mu * mu;
    float inv = rsqrtf(var + 1e-5f);
    float4 g4 = ((const float4*)g)[tid];
    float4 b4 = ((const float4*)bta)[tid];
    __half2 o0 = __floats2half2_rn((v.x - mu) * inv * g4.x + b4.x,
                                   (v.y - mu) * inv * g4.y + b4.y);
    __half2 o1 = __floats2half2_rn((v.z - mu) * inv * g4.z + b4.z,
                                   (v.w - mu) * inv * g4.w + b4.w);
    __half2* yp = (__half2*)(y + (size_t)row * D_) + tid * 2;
    yp[0] = o0; yp[1] = o1;
}

// ---------------- fp16 tensor-core GEMM 128x128, K-stage 32, 3-stage --------
// 3 smem stages (dynamic), wait_group 1 steady state: tile i+1 in flight
// during compute of tile i -> no load-latency exposure.
// EPI bit0: +bias  bit1: gelu  bit2: +res(fp32)
// OUTH: 1 -> C is __half*, 0 -> C is float*
#define HG_TILE_U32 (128 * 20)
#define HG_SMEM_BYTES (6 * HG_TILE_U32 * 4)   // 3 stages x (A + B) = 61440

template <int EPI, int OUTH>
__global__ __launch_bounds__(256, 2) void hgemm_kernel(
    const __half* __restrict__ A, const __half* __restrict__ Bt,
    void* __restrict__ Cv, const float* __restrict__ bias,
    const float* __restrict__ res, int M, int N, int K)
{
    extern __shared__ uint32_t dynsm[];
    uint32_t* As = dynsm;                       // [3][128][20]
    uint32_t* Bs = dynsm + 3 * HG_TILE_U32;     // [3][128][20]
    int tid = threadIdx.x;
    int lane = tid & 31, warp = tid >> 5;
    int g = lane >> 2, tg = lane & 3;
    int mw = (warp & 3) << 5;
    int nw = (warp >> 2) << 6;
    int bm = blockIdx.y, bn = blockIdx.x;
    const __half* Ab = A  + (size_t)bm * 128 * K;
    const __half* Bb = Bt + (size_t)bn * 128 * K;

    float acc[2][8][4];
    #pragma unroll
    for (int mi = 0; mi < 2; mi++)
        #pragma unroll
        for (int j = 0; j < 8; j++)
            #pragma unroll
            for (int q = 0; q < 4; q++) acc[mi][j][q] = 0.f;

    int lrow = tid >> 1;            // 0..127
    int lseg = (tid & 1) << 3;      // u32 offset 0 or 8

    uint32_t as0 = (uint32_t)__cvta_generic_to_shared(As);
    uint32_t bs0 = (uint32_t)__cvta_generic_to_shared(Bs);
    uint32_t lda = as0 + (uint32_t)((lrow * 20 + lseg) * 4);
    uint32_t ldb = bs0 + (uint32_t)((lrow * 20 + lseg) * 4);
    uint32_t aoff[2];
    #pragma unroll
    for (int mi = 0; mi < 2; mi++) {
        int row = mw + (mi << 4) + ((lane >> 3) & 1) * 8 + (lane & 7);
        int col = (lane >> 4) << 2;
        aoff[mi] = (uint32_t)((row * 20 + col) * 4);
    }
    uint32_t boff[4];
    #pragma unroll
    for (int jj = 0; jj < 4; jj++) {
        int row = nw + (jj << 4) + ((lane >> 4) << 3) + (lane & 7);
        int col = ((lane >> 3) & 1) << 2;
        boff[jj] = (uint32_t)((row * 20 + col) * 4);
    }
    const uint32_t TB = HG_TILE_U32 * 4;      // stage stride bytes

    int nk = K >> 5;
    // prefetch tiles 0 and 1 (separate commit groups)
    #pragma unroll
    for (int p = 0; p < 2; p++) {
        int kt = p << 5;
        cp_async16_s(lda + p * TB,      Ab + (size_t)lrow * K + kt + (lseg << 1));
        cp_async16_s(lda + p * TB + 16, Ab + (size_t)lrow * K + kt + (lseg << 1) + 8);
        cp_async16_s(ldb + p * TB,      Bb + (size_t)lrow * K + kt + (lseg << 1));
        cp_async16_s(ldb + p * TB + 16, Bb + (size_t)lrow * K + kt + (lseg << 1) + 8);
        CP_COMMIT();
    }

    int sb = 0, sp = 2;
    for (int it = 0; it < nk; it++) {
        if (it + 1 < nk) { CP_WAIT1(); } else { CP_WAIT0(); }
        __syncthreads();
        if (it + 2 < nk) {
            int kt = (it + 2) << 5;
            cp_async16_s(lda + sp * TB,      Ab + (size_t)lrow * K + kt + (lseg << 1));
            cp_async16_s(lda + sp * TB + 16, Ab + (size_t)lrow * K + kt + (lseg << 1) + 8);
            cp_async16_s(ldb + sp * TB,      Bb + (size_t)lrow * K + kt + (lseg << 1));
            cp_async16_s(ldb + sp * TB + 16, Bb + (size_t)lrow * K + kt + (lseg << 1) + 8);
            CP_COMMIT();
        }
        uint32_t ab  = as0 + sb * TB;
        uint32_t bb2 = bs0 + sb * TB;
        #pragma unroll
        for (int ks = 0; ks < 2; ks++) {
            uint32_t kbyte = (uint32_t)(ks * 32);
            uint32_t af[2][4], bf[8][2];
            #pragma unroll
            for (int mi = 0; mi < 2; mi++)
                ldmx4(af[mi][0], af[mi][1], af[mi][2], af[mi][3],
                      ab + aoff[mi] + kbyte);
            #pragma unroll
            for (int jj = 0; jj < 4; jj++)
                ldmx4(bf[2*jj][0], bf[2*jj][1], bf[2*jj+1][0], bf[2*jj+1][1],
                      bb2 + boff[jj] + kbyte);
            #pragma unroll
            for (int mi = 0; mi < 2; mi++)
                #pragma unroll
                for (int j = 0; j < 8; j++)
                    mma_f16(acc[mi][j], af[mi], bf[j]);
        }
        sb = (sb == 2) ? 0 : sb + 1;
        sp = (sp == 2) ? 0 : sp + 1;
    }

    #pragma unroll
    for (int mi = 0; mi < 2; mi++) {
        int r0 = bm * 128 + mw + (mi << 4) + g;
        int r1 = r0 + 8;
        #pragma unroll
        for (int j = 0; j < 8; j++) {
            int c = bn * 128 + nw + (j << 3) + (tg << 1);
            float v0 = acc[mi][j][0], v1 = acc[mi][j][1];
            float v2 = acc[mi][j][2], v3 = acc[mi][j][3];
            if (EPI & 1) {
                float2 bv = *(const float2*)(bias + c);
                v0 += bv.x; v1 += bv.y; v2 += bv.x; v3 += bv.y;
            }
            if (EPI & 2) {
                v0 = geluf(v0); v1 = geluf(v1);
                v2 = geluf(v2); v3 = geluf(v3);
            }
            if (EPI & 4) {
                float2 ra = *(const float2*)(res + (size_t)r0 * N + c);
                float2 rb = *(const float2*)(res + (size_t)r1 * N + c);
                v0 += ra.x; v1 += ra.y; v2 += rb.x; v3 += rb.y;
            }
            if (OUTH) {
                __half* Ch = (__half*)Cv;
                *(__half2*)(Ch + (size_t)r0 * N + c) = __floats2half2_rn(v0, v1);
                *(__half2*)(Ch + (size_t)r1 * N + c) = __floats2half2_rn(v2, v3);
            } else {
                float* Cf = (float*)Cv;
                float2 w0 = { v0, v1 }, w1 = { v2, v3 };
                *(float2*)(Cf + (size_t)r0 * N + c) = w0;
                *(float2*)(Cf + (size_t)r1 * N + c) = w1;
            }
        }
    }
}

// ---------------- flash attention, fp16 mma + full ldmatrix (R16) -----------
#define FQP 36
#define FLASH_SMEM_U32 (6*64*FQP + 256)
#define FLASH_SMEM_BYTES (FLASH_SMEM_U32 * 4)

__global__ __launch_bounds__(256, 2) void flash_attn_kernel()
{
    extern __shared__ uint32_t usm[];
    uint32_t* Qs = usm;                    // [64][FQP]
    uint32_t* Ks = Qs + 64 * FQP;          // [2][64][FQP]
    uint32_t* Vs = Ks + 2 * 64 * FQP;      // [2][64][FQP]
    uint32_t* Ps = Vs + 2 * 64 * FQP;      // [64][FQP]
    float* redm  = (float*)(Ps + 64 * FQP); // [128]
    float* reds  = redm + 128;              // [128]

    int bh = blockIdx.y;
    int b = bh >> 4, h = bh & 15;
    int t0 = blockIdx.x * 64;
    int tid = threadIdx.x;
    int lane = tid & 31, warp = tid >> 5;
    int g = lane >> 2, tg = lane & 3;
    int wm = warp & 3, wn = warp >> 2;
    int m0r = (wm << 4) + g;
    int nb  = wn << 5;

    uint32_t a_off;
    {
        int row = (wm << 4) + ((lane >> 3) & 1) * 8 + (lane & 7);
        int col = (lane >> 4) << 2;
        a_off = (uint32_t)((row * FQP + col) * 4);
    }
    uint32_t k_off[2];
    #pragma unroll
    for (int jj = 0; jj < 2; jj++) {
        int row = nb + (jj << 4) + ((lane >> 4) << 3) + (lane & 7);
        int col = ((lane >> 3) & 1) << 2;
        k_off[jj] = (uint32_t)((row * FQP + col) * 4);
    }
    uint32_t v_off[2];
    #pragma unroll
    for (int jp = 0; jp < 2; jp++) {
        int row = (((lane >> 3) & 1) << 3) + (lane & 7);
        int colh = nb + (jp << 4) + ((lane >> 4) << 3);
        v_off[jp] = (uint32_t)(row * FQP * 4 + colh * 2);
    }

    const __half* qbase = g_qkv + ((size_t)b * T_) * TD3_ + h * 64;
    int lrow = tid >> 3;
    int lch  = tid & 7;

    #pragma unroll
    for (int i = 0; i < 2; i++) {
        int row = lrow + i * 32;
        cp_async16(&Qs[row * FQP + lch * 4], qbase + (size_t)(t0 + row) * TD3_ + lch * 8);
    }
    CP_COMMIT();
    #pragma unroll
    for (int i = 0; i < 2; i++) {
        int row = lrow + i * 32;
        cp_async16(&Ks[row * FQP + lch * 4], qbase + 1024 + (size_t)row * TD3_ + lch * 8);
        cp_async16(&Vs[row * FQP + lch * 4], qbase + 2048 + (size_t)row * TD3_ + lch * 8);
    }
    CP_COMMIT();

    uint32_t qs_addr = (uint32_t)__cvta_generic_to_shared(Qs);
    uint32_t ps_addr = (uint32_t)__cvta_generic_to_shared(Ps);

    float accO[4][4];
    #pragma unroll
    for (int j = 0; j < 4; j++)
        #pragma unroll
        for (int q = 0; q < 4; q++) accO[j][q] = 0.f;
    float m0 = -3.0e38f, m1 = -3.0e38f, l0 = 0.f, l1 = 0.f;

    for (int st = 0; st < 16; st++) {
        int buf = st & 1;
        uint32_t* Kb = Ks + buf * 64 * FQP;
        uint32_t* Vb = Vs + buf * 64 * FQP;
        uint32_t kb_addr = (uint32_t)__cvta_generic_to_shared(Kb);
        uint32_t vb_addr = (uint32_t)__cvta_generic_to_shared(Vb);
        CP_WAIT0();
        __syncthreads();
        if (st + 1 < 16) {
            int s1 = (st + 1) * 64;
            uint32_t* Kn = Ks + (buf ^ 1) * 64 * FQP;
            uint32_t* Vn = Vs + (buf ^ 1) * 64 * FQP;
            #pragma unroll
            for (int i = 0; i < 2; i++) {
                int row = lrow + i * 32;
                cp_async16(&Kn[row * FQP + lch * 4], qbase + 1024 + (size_t)(s1 + row) * TD3_ + lch * 8);
                cp_async16(&Vn[row * FQP + lch * 4], qbase + 2048 + (size_t)(s1 + row) * TD3_ + lch * 8);
            }
            CP_COMMIT();
        }

        float sacc[4][4];
        #pragma unroll
        for (int j = 0; j < 4; j++)
            #pragma unroll
            for (int q = 0; q < 4; q++) sacc[j][q] = 0.f;
        #pragma unroll
        for (int ks = 0; ks < 4; ks++) {
            uint32_t kbyte = (uint32_t)(ks * 32);
            uint32_t af[4], bf[4][2];
            ldmx4(af[0], af[1], af[2], af[3], qs_addr + a_off + kbyte);
            #pragma unroll
            for (int jj = 0; jj < 2; jj++)
                ldmx4(bf[2*jj][0], bf[2*jj][1], bf[2*jj+1][0], bf[2*jj+1][1],
                      kb_addr + k_off[jj] + kbyte);
            #pragma unroll
            for (int j = 0; j < 4; j++) mma_f16(sacc[j], af, bf[j]);
        }

        float rmax0 = -3.0e38f, rmax1 = -3.0e38f;
        #pragma unroll
        for (int j = 0; j < 4; j++) {
            #pragma unroll
            for (int q = 0; q < 4; q++) sacc[j][q] *= 0.125f;
            rmax0 = fmaxf(rmax0, fmaxf(sacc[j][0], sacc[j][1]));
            rmax1 = fmaxf(rmax1, fmaxf(sacc[j][2], sacc[j][3]));
        }
        rmax0 = fmaxf(rmax0, __shfl_xor_sync(0xffffffffu, rmax0, 1));
        rmax0 = fmaxf(rmax0, __shfl_xor_sync(0xffffffffu, rmax0, 2));
        rmax1 = fmaxf(rmax1, __shfl_xor_sync(0xffffffffu, rmax1, 1));
        rmax1 = fmaxf(rmax1, __shfl_xor_sync(0xffffffffu, rmax1, 2));
        if (tg == 0) {
            redm[m0r * 2 + wn]       = rmax0;
            redm[(m0r + 8) * 2 + wn] = rmax1;
        }
        __syncthreads();
        float mn0 = fmaxf(m0, fmaxf(redm[m0r * 2], redm[m0r * 2 + 1]));
        float mn1 = fmaxf(m1, fmaxf(redm[(m0r + 8) * 2], redm[(m0r + 8) * 2 + 1]));
        float alpha0 = __expf(m0 - mn0);
        float alpha1 = __expf(m1 - mn1);
        m0 = mn0; m1 = mn1;

        float rs0 = 0.f, rs1 = 0.f;
        #pragma unroll
        for (int j = 0; j < 4; j++) {
            float p00 = __expf(sacc[j][0] - mn0);
            float p01 = __expf(sacc[j][1] - mn0);
            float p10 = __expf(sacc[j][2] - mn1);
            float p11 = __expf(sacc[j][3] - mn1);
            rs0 += p00 + p01; rs1 += p10 + p11;
            int cu = (nb >> 1) + (j << 2) + tg;
            Ps[m0r * FQP + cu]       = h2u(__floats2half2_rn(p00, p01));
            Ps[(m0r + 8) * FQP + cu] = h2u(__floats2half2_rn(p10, p11));
        }
        rs0 += __shfl_xor_sync(0xffffffffu, rs0, 1);
        rs0 += __shfl_xor_sync(0xffffffffu, rs0, 2);
        rs1 += __shfl_xor_sync(0xffffffffu, rs1, 1);
        rs1 += __shfl_xor_sync(0xffffffffu, rs1, 2);
        if (tg == 0) {
            reds[m0r * 2 + wn]       = rs0;
            reds[(m0r + 8) * 2 + wn] = rs1;
        }
        #pragma unroll
        for (int j = 0; j < 4; j++) {
            accO[j][0] *= alpha0; accO[j][1] *= alpha0;
            accO[j][2] *= alpha1; accO[j][3] *= alpha1;
        }
        __syncthreads();
        l0 = l0 * alpha0 + reds[m0r * 2] + reds[m0r * 2 + 1];
        l1 = l1 * alpha1 + reds[(m0r + 8) * 2] + reds[(m0r + 8) * 2 + 1];

        #pragma unroll
        for (int ks = 0; ks < 4; ks++) {
            uint32_t kbyte = (uint32_t)(ks * 32);
            uint32_t vrow  = (uint32_t)(ks * 16 * FQP * 4);
            uint32_t af[4], bf[4][2];
            ldmx4(af[0], af[1], af[2], af[3], ps_addr + a_off + kbyte);
            #pragma unroll
            for (int jp = 0; jp < 2; jp++)
                ldmx4_trans(bf[2*jp][0], bf[2*jp][1], bf[2*jp+1][0], bf[2*jp+1][1],
                            vb_addr + v_off[jp] + vrow);
            #pragma unroll
            for (int j = 0; j < 4; j++) mma_f16(accO[j], af, bf[j]);
        }
    }

    float inv0 = 1.0f / l0;
    float inv1 = 1.0f / l1;
    __half* out0 = g_ctx + ((size_t)b * T_ + t0 + m0r) * D_ + h * 64;
    __half* out1 = out0 + (size_t)8 * D_;
    #pragma unroll
    for (int j = 0; j < 4; j++) {
        int col = nb + (j << 3) + (tg << 1);
        *(__half2*)(out0 + col) = __floats2half2_rn(accO[j][0] * inv0, accO[j][1] * inv0);
        *(__half2*)(out1 + col) = __floats2half2_rn(accO[j][2] * inv1, accO[j][3] * inv1);
    }
}

// ---------------- launcher --------------------------------------------------
extern "C" void kernel_launch(void* const* d_in, const int* in_sizes, int n_in,
                              void* d_out, int out_size)
{
    const float* x    = (const float*)d_in[0];
    const float* ln1g = (const float*)d_in[1];
    const float* ln1b = (const float*)d_in[2];
    const float* ln2g = (const float*)d_in[3];
    const float* ln2b = (const float*)d_in[4];
    const float* Wq   = (const float*)d_in[5];
    const float* bq   = (const float*)d_in[6];
    const float* Wk   = (const float*)d_in[7];
    const float* bk   = (const float*)d_in[8];
    const float* Wv   = (const float*)d_in[9];
    const float* bv   = (const float*)d_in[10];
    const float* Wo   = (const float*)d_in[11];
    const float* bo   = (const float*)d_in[12];
    const float* W1   = (const float*)d_in[13];
    const float* b1   = (const float*)d_in[14];
    const float* W2   = (const float*)d_in[15];
    const float* b2   = (const float*)d_in[16];
    float* out = (float*)d_out;

    static __half* h_     = nullptr;
    static __half* qkv_   = nullptr;
    static float*  wcat_  = nullptr;
    static __half* wcatT_ = nullptr;
    static float*  bcat_  = nullptr;
    static __half* ctx_   = nullptr;
    static __half* ffa_   = nullptr;
    static __half* wrnd_  = nullptr;
    if (!h_) {   // pointer cache only — identical work every call
        cudaGetSymbolAddress((void**)&h_,     g_h);
        cudaGetSymbolAddress((void**)&qkv_,   g_qkv);
        cudaGetSymbolAddress((void**)&wcat_,  g_wcat);
        cudaGetSymbolAddress((void**)&wcatT_, g_wcatT);
        cudaGetSymbolAddress((void**)&bcat_,  g_bcat);
        cudaGetSymbolAddress((void**)&ctx_,   g_ctx);
        cudaGetSymbolAddress((void**)&ffa_,   g_ffa);
        cudaGetSymbolAddress((void**)&wrnd_,  g_wrndh);
        cudaFuncSetAttribute(flash_attn_kernel,
                             cudaFuncAttributeMaxDynamicSharedMemorySize, FLASH_SMEM_BYTES);
        cudaFuncSetAttribute(hgemm_kernel<1, 1>,
                             cudaFuncAttributeMaxDynamicSharedMemorySize, HG_SMEM_BYTES);
        cudaFuncSetAttribute(hgemm_kernel<5, 0>,
                             cudaFuncAttributeMaxDynamicSharedMemorySize, HG_SMEM_BYTES);
        cudaFuncSetAttribute(hgemm_kernel<3, 1>,
                             cudaFuncAttributeMaxDynamicSharedMemorySize, HG_SMEM_BYTES);
    }
    __half* woT = wrnd_;
    __half* w1T = wrnd_ + (size_t)D_ * D_;
    __half* w2T = wrnd_ + (size_t)D_ * D_ + (size_t)D_ * FF_;

    // 1) weight prep: repack, then transpose+halve everything to [N][K]
    repack_kernel<<<(D_ * TD3_ + 255) / 256, 256>>>(Wq, Wk, Wv, bq, bk, bv);
    transTh_kernel<<<dim3(TD3_ / 32, D_ / 32), 256>>>(wcat_, wcatT_, D_, TD3_);
    transTh_kernel<<<dim3(D_ / 32, D_ / 32), 256>>>(Wo, woT, D_, D_);
    transTh_kernel<<<dim3(FF_ / 32, D_ / 32), 256>>>(W1, w1T, D_, FF_);
    transTh_kernel<<<dim3(D_ / 32, FF_ / 32), 256>>>(W2, w2T, FF_, D_);
    // 2) ln1 -> h (half)
    ln_kernel<<<BT_, 256>>>(x, ln1g, ln1b, h_);
    // 3) QKV = h @ Wcat + bcat -> half
    hgemm_kernel<1, 1><<<dim3(TD3_ / 128, BT_ / 128), 256, HG_SMEM_BYTES>>>(
        h_, wcatT_, qkv_, bcat_, nullptr, BT_, TD3_, D_);
    // 4-6) fused attention -> ctx (half)
    flash_attn_kernel<<<dim3(16, B_ * H_), 256, FLASH_SMEM_BYTES>>>();
    // 7) X1 = x + ctx @ Wo + bo -> out (fp32)
    hgemm_kernel<5, 0><<<dim3(D_ / 128, BT_ / 128), 256, HG_SMEM_BYTES>>>(
        ctx_, woT, out, bo, x, BT_, D_, D_);
    // 8) ln2 -> h (half)
    ln_kernel<<<BT_, 256>>>(out, ln2g, ln2b, h_);
    // 9) ffa = gelu(h @ W1 + b1) -> half
    hgemm_kernel<3, 1><<<dim3(FF_ / 128, BT_ / 128), 256, HG_SMEM_BYTES>>>(
        h_, w1T, ffa_, b1, nullptr, BT_, FF_, D_);
    // 10) out = X1 + ffa @ W2 + b2 -> fp32
    hgemm_kernel<5, 0><<<dim3(D_ / 128, BT_ / 128), 256, HG_SMEM_BYTES>>>(
        ffa_, w2T, out, b2, out, BT_, D_, FF_);
}